// round 1
// baseline (speedup 1.0000x reference)
#include <cuda_runtime.h>
#include <math.h>

#define B_ 2
#define S_ 2048
#define E_ 1024
#define H_ 16
#define D_ 64
#define WIN_ 256

// ---------------- scratch (device globals, allocation-free) ----------------
__device__ float g_q[B_*H_*S_*D_];     // [b][h][s][d]
__device__ float g_k[B_*H_*S_*D_];
__device__ float g_v[B_*H_*S_*D_];
__device__ float g_y[B_*S_*E_];        // attention out, [b][s][h*64+d]
__device__ float g_cos[S_*32];
__device__ float g_sin[S_*32];

// ---------------- RoPE table ----------------
__global__ void rope_table_kernel() {
    int i = blockIdx.x * blockDim.x + threadIdx.x;
    if (i >= S_ * 32) return;
    int s = i >> 5, j = i & 31;
    double invf = pow(10000.0, -(double)j / 32.0);
    double ang  = (double)s * invf;
    g_cos[i] = (float)cos(ang);
    g_sin[i] = (float)sin(ang);
}

// ---------------- fp32 NT GEMM: C = A @ W^T ----------------
// A: [M=4096, 1024] row-major, W: [1024, 1024] row-major (out-feature rows)
// mode 0: C row-major [M,1024]; mode 1: C in [b][h][s][d]
__device__ __forceinline__ void gemm_body(const float* __restrict__ A,
                                          const float* __restrict__ Wt,
                                          float* __restrict__ C, int mode)
{
    __shared__ float As[16][128];
    __shared__ float Ws[16][128];
    const int tid = threadIdx.x;
    const int m0 = blockIdx.y << 7;
    const int n0 = blockIdx.x << 7;
    const int rowA0 = (tid >> 4) << 3;   // 0..120
    const int col0  = (tid & 15) << 3;   // 0..120

    float acc[8][8];
    #pragma unroll
    for (int i = 0; i < 8; ++i)
        #pragma unroll
        for (int j = 0; j < 8; ++j) acc[i][j] = 0.f;

    for (int kb = 0; kb < E_; kb += 16) {
        __syncthreads();
        #pragma unroll
        for (int u = 0; u < 2; ++u) {
            int f4  = tid + (u << 8);          // 0..511
            int row = f4 >> 2;                 // 0..127
            int kc  = (f4 & 3) << 2;           // 0,4,8,12
            float4 va = *(const float4*)(A  + (size_t)(m0 + row) * E_ + kb + kc);
            As[kc+0][row] = va.x; As[kc+1][row] = va.y;
            As[kc+2][row] = va.z; As[kc+3][row] = va.w;
            float4 vw = *(const float4*)(Wt + (size_t)(n0 + row) * E_ + kb + kc);
            Ws[kc+0][row] = vw.x; Ws[kc+1][row] = vw.y;
            Ws[kc+2][row] = vw.z; Ws[kc+3][row] = vw.w;
        }
        __syncthreads();
        #pragma unroll
        for (int kk = 0; kk < 16; ++kk) {
            float a[8], b[8];
            *(float4*)&a[0] = *(const float4*)&As[kk][rowA0];
            *(float4*)&a[4] = *(const float4*)&As[kk][rowA0 + 4];
            *(float4*)&b[0] = *(const float4*)&Ws[kk][col0];
            *(float4*)&b[4] = *(const float4*)&Ws[kk][col0 + 4];
            #pragma unroll
            for (int i = 0; i < 8; ++i)
                #pragma unroll
                for (int j = 0; j < 8; ++j)
                    acc[i][j] += a[i] * b[j];
        }
    }

    #pragma unroll
    for (int i = 0; i < 8; ++i) {
        int m = m0 + rowA0 + i;
        #pragma unroll
        for (int j = 0; j < 8; ++j) {
            int n = n0 + col0 + j;
            if (mode == 0) {
                C[(size_t)m * E_ + n] = acc[i][j];
            } else {
                int b_ = m >> 11, s = m & (S_ - 1);
                int h  = n >> 6,  d = n & 63;
                C[((((size_t)b_ * H_ + h) * S_ + s) << 6) + d] = acc[i][j];
            }
        }
    }
}

__global__ __launch_bounds__(256) void gemm_qkv_kernel(
    const float* __restrict__ A, const float* __restrict__ Wt, int which)
{
    float* dst = (which == 0) ? g_q : (which == 1) ? g_k : g_v;
    gemm_body(A, Wt, dst, 1);
}

__global__ __launch_bounds__(256) void gemm_out_kernel(
    const float* __restrict__ Wt, float* __restrict__ C)
{
    gemm_body(g_y, Wt, C, 0);
}

// ---------------- RoPE apply (in place on g_q, g_k) ----------------
__global__ void rope_apply_kernel() {
    int i = blockIdx.x * blockDim.x + threadIdx.x;  // over B*H*S*32
    if (i >= B_ * H_ * S_ * 32) return;
    int d = i & 31;
    int r = i >> 5;              // (b*H+h)*S + s
    int s = r & (S_ - 1);
    float c  = g_cos[(s << 5) + d];
    float sn = g_sin[(s << 5) + d];
    {
        float* p = g_q + ((size_t)r << 6);
        float x1 = p[d], x2 = p[d + 32];
        p[d]      = x1 * c - x2 * sn;
        p[d + 32] = x2 * c + x1 * sn;
    }
    {
        float* p = g_k + ((size_t)r << 6);
        float x1 = p[d], x2 = p[d + 32];
        p[d]      = x1 * c - x2 * sn;
        p[d + 32] = x2 * c + x1 * sn;
    }
}

// ---------------- windowed flash attention ----------------
// grid (S/128, H, B), 128 threads; thread t owns query q0+t.
__global__ __launch_bounds__(128) void attn_kernel() {
    __shared__ float Ks[64][64];
    __shared__ float Vs[64][64];
    const int t  = threadIdx.x;
    const int q0 = blockIdx.x << 7;
    const int h  = blockIdx.y;
    const int b  = blockIdx.z;
    const size_t bh = (size_t)(b * H_ + h) * S_;
    const int sq = q0 + t;

    float qreg[64];
    {
        const float4* qp = (const float4*)(g_q + ((bh + sq) << 6));
        #pragma unroll
        for (int u = 0; u < 16; ++u) {
            float4 v = qp[u];
            qreg[u*4+0] = v.x * 0.125f;
            qreg[u*4+1] = v.y * 0.125f;
            qreg[u*4+2] = v.z * 0.125f;
            qreg[u*4+3] = v.w * 0.125f;
        }
    }

    float m = -1e30f, l = 0.f;
    float o[64];
    #pragma unroll
    for (int d = 0; d < 64; ++d) o[d] = 0.f;

    const int kt0 = (q0 >= WIN_) ? ((q0 - WIN_ + 1) >> 6) : 0;
    const int kt1 = (q0 + 127) >> 6;

    for (int kt = kt0; kt <= kt1; ++kt) {
        const int jb = kt << 6;
        __syncthreads();
        #pragma unroll
        for (int u = 0; u < 8; ++u) {
            int f4  = t + (u << 7);     // 0..1023
            int row = f4 >> 4;          // 0..63
            int c4  = (f4 & 15) << 2;   // 0..60
            *(float4*)&Ks[row][c4] = *(const float4*)(g_k + ((bh + jb + row) << 6) + c4);
            *(float4*)&Vs[row][c4] = *(const float4*)(g_v + ((bh + jb + row) << 6) + c4);
        }
        __syncthreads();

        for (int js = 0; js < 64; js += 16) {
            float sc[16];
            float mx = -1e30f;
            #pragma unroll
            for (int jj = 0; jj < 16; ++jj) {
                int jpos = jb + js + jj;
                float dot = 0.f;
                #pragma unroll
                for (int d = 0; d < 64; ++d)
                    dot += qreg[d] * Ks[js + jj][d];
                bool ok = (jpos <= sq) && (sq - jpos < WIN_);
                sc[jj] = ok ? dot : -1e30f;
                mx = fmaxf(mx, sc[jj]);
            }
            if (mx > -1e29f) {
                float mnew  = fmaxf(m, mx);
                float alpha = __expf(m - mnew);
                l *= alpha;
                #pragma unroll
                for (int d = 0; d < 64; ++d) o[d] *= alpha;
                #pragma unroll
                for (int jj = 0; jj < 16; ++jj) {
                    float p = __expf(sc[jj] - mnew);
                    l += p;
                    #pragma unroll
                    for (int d = 0; d < 64; ++d)
                        o[d] += p * Vs[js + jj][d];
                }
                m = mnew;
            }
        }
    }

    float inv = 1.f / l;
    float* yp = g_y + (size_t)(b * S_ + sq) * E_ + (h << 6);
    #pragma unroll
    for (int d = 0; d < 64; ++d) yp[d] = o[d] * inv;
}

// ---------------- launch ----------------
extern "C" void kernel_launch(void* const* d_in, const int* in_sizes, int n_in,
                              void* d_out, int out_size)
{
    const float* x  = (const float*)d_in[0];
    const float* Wq = (const float*)d_in[1];
    const float* Wk = (const float*)d_in[2];
    const float* Wv = (const float*)d_in[3];
    const float* Wo = (const float*)d_in[4];
    float* out = (float*)d_out;

    rope_table_kernel<<<(S_ * 32 + 255) / 256, 256>>>();

    dim3 gg(E_ / 128, (B_ * S_) / 128);   // (8, 32)
    gemm_qkv_kernel<<<gg, 256>>>(x, Wq, 0);
    gemm_qkv_kernel<<<gg, 256>>>(x, Wk, 1);
    gemm_qkv_kernel<<<gg, 256>>>(x, Wv, 2);

    rope_apply_kernel<<<(B_ * H_ * S_ * 32 + 255) / 256, 256>>>();

    dim3 ga(S_ / 128, H_, B_);
    attn_kernel<<<ga, 128>>>();

    gemm_out_kernel<<<gg, 256>>>(Wo, out);
}

// round 3
// speedup vs baseline: 2.1385x; 2.1385x over previous
#include <cuda_runtime.h>
#include <cuda_fp16.h>
#include <math.h>
#include <stdint.h>

#define B_ 2
#define S_ 2048
#define E_ 1024
#define H_ 16
#define D_ 64
#define WIN_ 256
#define M_TOTAL (B_*S_)          // 4096
#define NCH 16                    // K chunks of 64

// ---------------- scratch (device globals, allocation-free) ----------------
__device__ float g_q[B_*H_*S_*D_];     // [b][h][s][d] fp32 (post-RoPE)
__device__ float g_k[B_*H_*S_*D_];
__device__ float g_v[B_*H_*S_*D_];
// pre-tiled + pre-swizzled fp16 hi/lo operands:
// x/y: [kchunk 16][row 4096][64], swizzled 16B-chunks by (row&7)
// w:   [z 4][kchunk 16][n 1024][64], swizzled by (n&7)
__device__ __align__(1024) __half g_xh[NCH*M_TOTAL*64];
__device__ __align__(1024) __half g_xl[NCH*M_TOTAL*64];
__device__ __align__(1024) __half g_wh[4*NCH*E_*64];
__device__ __align__(1024) __half g_wl[4*NCH*E_*64];
__device__ __align__(1024) __half g_yh[NCH*M_TOTAL*64];
__device__ __align__(1024) __half g_yl[NCH*M_TOTAL*64];
__device__ float g_cos[S_*32];
__device__ float g_sin[S_*32];

// ---------------- PTX helpers ----------------
__device__ __forceinline__ uint32_t smem_u32(const void* p) {
    uint32_t a;
    asm("{ .reg .u64 t; cvta.to.shared.u64 t, %1; cvt.u32.u64 %0, t; }"
        : "=r"(a) : "l"(p));
    return a;
}

__device__ __forceinline__ void mbar_wait(uint32_t mbar, uint32_t parity) {
    asm volatile(
        "{\n\t.reg .pred P;\n\t"
        "WL%=:\n\t"
        "mbarrier.try_wait.parity.acquire.cta.shared::cta.b64 P, [%0], %1, 0x989680;\n\t"
        "@P bra WD%=;\n\t"
        "bra WL%=;\n\t"
        "WD%=:\n\t}"
        :: "r"(mbar), "r"(parity) : "memory");
}

__device__ __forceinline__ void bulk_cp(uint32_t dst, const void* src, uint32_t bytes,
                                        uint32_t mbar) {
    asm volatile(
        "cp.async.bulk.shared::cluster.global.mbarrier::complete_tx::bytes [%0], [%1], %2, [%3];"
        :: "r"(dst), "l"(src), "r"(bytes), "r"(mbar) : "memory");
}

#define LDSM4(r, a) \
    asm volatile("ldmatrix.sync.aligned.m8n8.x4.shared.b16 {%0,%1,%2,%3}, [%4];" \
        : "=r"((r)[0]), "=r"((r)[1]), "=r"((r)[2]), "=r"((r)[3]) : "r"(a))

#define MMA16816(c, a, b) \
    asm volatile("mma.sync.aligned.m16n8k16.row.col.f32.f16.f16.f32 " \
        "{%0,%1,%2,%3}, {%4,%5,%6,%7}, {%8,%9}, {%0,%1,%2,%3};" \
        : "+f"((c)[0]), "+f"((c)[1]), "+f"((c)[2]), "+f"((c)[3]) \
        : "r"((a)[0]), "r"((a)[1]), "r"((a)[2]), "r"((a)[3]), \
          "r"((b)[0]), "r"((b)[1]))

// ---------------- RoPE table ----------------
__global__ void rope_table_kernel() {
    int i = blockIdx.x * blockDim.x + threadIdx.x;
    if (i >= S_ * 32) return;
    int s = i >> 5, j = i & 31;
    double invf = pow(10000.0, -(double)j / 32.0);
    double ang  = (double)s * invf;
    g_cos[i] = (float)cos(ang);
    g_sin[i] = (float)sin(ang);
}

// ---------------- fp32 -> pre-tiled pre-swizzled fp16 hi/lo ----------------
__device__ __forceinline__ size_t xy_idx(int ci, int m, int k63) {
    int c = k63 >> 3, w = k63 & 7;
    return (((size_t)ci * M_TOTAL + m) << 6) + (((c ^ (m & 7)) << 3) | w);
}

__global__ void conv_x_kernel(const float* __restrict__ x) {
    int i = blockIdx.x * blockDim.x + threadIdx.x;
    if (i >= M_TOTAL * E_) return;
    int m = i >> 10, k = i & 1023;
    float v = x[i];
    __half h = __float2half_rn(v);
    __half l = __float2half_rn(v - __half2float(h));
    size_t idx = xy_idx(k >> 6, m, k & 63);
    g_xh[idx] = h; g_xl[idx] = l;
}

__global__ void conv_w_kernel(const float* __restrict__ Wq, const float* __restrict__ Wk,
                              const float* __restrict__ Wv, const float* __restrict__ Wo) {
    int i = blockIdx.x * blockDim.x + threadIdx.x;
    if (i >= 4 * E_ * E_) return;
    int z = i >> 20;
    int j = i & (E_ * E_ - 1);
    int n = j >> 10, k = j & 1023;
    const float* p = (z == 0) ? Wq : (z == 1) ? Wk : (z == 2) ? Wv : Wo;
    float v = p[j];
    __half h = __float2half_rn(v);
    __half l = __float2half_rn(v - __half2float(h));
    int c = (k >> 3) & 7, w = k & 7;
    size_t idx = ((((size_t)z * NCH + (k >> 6)) * E_ + n) << 6)
               + (((c ^ (n & 7)) << 3) | w);
    g_wh[idx] = h; g_wl[idx] = l;
}

// ---------------- HMMA fp16-split GEMM: C = A @ W^T ----------------
// 128x128 tile, K chunks of 64, 256 threads (8 warps, warp tile 32x64).
// mode 1: A = x, z = blockIdx.z (Wq/Wk/Wv); writes g_q/g_k/g_v with RoPE fused.
// mode 0: A = y, W = Wo (z=3); writes fp32 row-major into Cout.
#define TILE_A 16384
#define STAGE_B 65536
#define SMEM_BYTES (1024 + 2*STAGE_B)

__global__ __launch_bounds__(256) void gemm_f16_kernel(int mode, float* __restrict__ Cout)
{
    extern __shared__ char smraw[];
    const uint32_t raw = smem_u32(smraw);
    const uint32_t HDR = (raw + 1023) & ~1023u;
    const uint32_t TIL = HDR + 1024;

    const int tid  = threadIdx.x;
    const int lane = tid & 31;
    const int wid  = tid >> 5;
    const int wm   = wid & 3;      // 4 warps over M (32 each)
    const int wn   = wid >> 2;     // 2 warps over N (64 each)
    const int sub  = lane >> 3;
    const int n0 = blockIdx.x << 7;
    const int m0 = blockIdx.y << 7;
    const int z  = (mode == 1) ? (int)blockIdx.z : 3;

    const __half* __restrict__ Ah = (mode == 1) ? g_xh : g_yh;
    const __half* __restrict__ Al = (mode == 1) ? g_xl : g_yl;

    if (tid == 0) {
        asm volatile("mbarrier.init.shared.b64 [%0], %1;" :: "r"(HDR),     "r"(1u) : "memory");
        asm volatile("mbarrier.init.shared.b64 [%0], %1;" :: "r"(HDR + 8), "r"(1u) : "memory");
    }
    __syncthreads();

    float acc[2][8][4];
    #pragma unroll
    for (int mi = 0; mi < 2; ++mi)
        #pragma unroll
        for (int ng = 0; ng < 8; ++ng)
            #pragma unroll
            for (int j = 0; j < 4; ++j) acc[mi][ng][j] = 0.f;

    // producer: issue chunk ci into stage st
    auto issue = [&](int ci, int st) {
        uint32_t mb = HDR + st * 8;
        uint32_t db = TIL + st * STAGE_B;
        asm volatile("mbarrier.arrive.expect_tx.shared.b64 _, [%0], %1;"
                     :: "r"(mb), "r"((uint32_t)STAGE_B) : "memory");
        bulk_cp(db,              Ah   + (((size_t)ci * M_TOTAL + m0) << 6), TILE_A, mb);
        bulk_cp(db + TILE_A,     Al   + (((size_t)ci * M_TOTAL + m0) << 6), TILE_A, mb);
        bulk_cp(db + 2 * TILE_A, g_wh + ((((size_t)z * NCH + ci) * E_ + n0) << 6), TILE_A, mb);
        bulk_cp(db + 3 * TILE_A, g_wl + ((((size_t)z * NCH + ci) * E_ + n0) << 6), TILE_A, mb);
    };

    if (tid == 0) issue(0, 0);

    for (int i = 0; i < NCH; ++i) {
        if (i + 1 < NCH && tid == 0) issue(i + 1, (i + 1) & 1);
        const int st = i & 1;
        mbar_wait(HDR + st * 8, (uint32_t)((i >> 1) & 1));
        const uint32_t base = TIL + st * STAGE_B;

        #pragma unroll
        for (int ks = 0; ks < 4; ++ks) {
            uint32_t Af[2][2][4];
            {
                const int ar0 = wm * 32 + (lane & 7) + ((sub & 1) << 3);
                const int akc = ks * 2 + (sub >> 1);
                #pragma unroll
                for (int mi = 0; mi < 2; ++mi) {
                    int r = ar0 + mi * 16;
                    uint32_t off = (uint32_t)(r * 128 + ((akc ^ (r & 7)) << 4));
                    LDSM4(Af[0][mi], base + off);
                    LDSM4(Af[1][mi], base + TILE_A + off);
                }
            }
            uint32_t Bf[2][4][4];
            {
                const int br0 = wn * 64 + (lane & 7) + ((sub >> 1) << 3);
                const int bkc = ks * 2 + (sub & 1);
                #pragma unroll
                for (int g = 0; g < 4; ++g) {
                    int r = br0 + g * 16;
                    uint32_t off = (uint32_t)(r * 128 + ((bkc ^ (r & 7)) << 4));
                    LDSM4(Bf[0][g], base + 2 * TILE_A + off);
                    LDSM4(Bf[1][g], base + 3 * TILE_A + off);
                }
            }
            #pragma unroll
            for (int mi = 0; mi < 2; ++mi)
                #pragma unroll
                for (int ng = 0; ng < 8; ++ng) {
                    const int g = ng >> 1, o = (ng & 1) << 1;
                    MMA16816(acc[mi][ng], Af[0][mi], &Bf[0][g][o]);   // hh
                    MMA16816(acc[mi][ng], Af[0][mi], &Bf[1][g][o]);   // h*l
                    MMA16816(acc[mi][ng], Af[1][mi], &Bf[0][g][o]);   // l*h
                }
        }
        __syncthreads();
    }

    // ---- epilogue (from registers) ----
    const int col2 = (lane & 3) << 1;
    const int h = (n0 >> 6) + wn;
    #pragma unroll
    for (int mi = 0; mi < 2; ++mi) {
        #pragma unroll
        for (int rr = 0; rr < 2; ++rr) {
            const int m = m0 + wm * 32 + mi * 16 + rr * 8 + (lane >> 2);
            if (mode == 0) {
                float* dp = Cout + (size_t)m * E_ + n0 + wn * 64;
                #pragma unroll
                for (int ng = 0; ng < 8; ++ng) {
                    float2 v = make_float2(acc[mi][ng][rr * 2], acc[mi][ng][rr * 2 + 1]);
                    *(float2*)(dp + ng * 8 + col2) = v;
                }
            } else {
                const int bb = m >> 11, ss = m & (S_ - 1);
                float* dst = ((z == 0) ? g_q : (z == 1) ? g_k : g_v)
                             + (((size_t)(bb * H_ + h) * S_ + ss) << 6);
                if (z == 2) {
                    #pragma unroll
                    for (int ng = 0; ng < 8; ++ng) {
                        float2 v = make_float2(acc[mi][ng][rr * 2], acc[mi][ng][rr * 2 + 1]);
                        *(float2*)(dst + ng * 8 + col2) = v;
                    }
                } else {
                    #pragma unroll
                    for (int ng = 0; ng < 4; ++ng)
                        #pragma unroll
                        for (int jj = 0; jj < 2; ++jj) {
                            const int d = ng * 8 + col2 + jj;
                            float x1 = acc[mi][ng][rr * 2 + jj];
                            float x2 = acc[mi][ng + 4][rr * 2 + jj];
                            float c  = g_cos[(ss << 5) + d];
                            float sn = g_sin[(ss << 5) + d];
                            dst[d]      = x1 * c - x2 * sn;
                            dst[d + 32] = x2 * c + x1 * sn;
                        }
                }
            }
        }
    }
}

// ---------------- windowed flash attention (SIMT, fp32) ----------------
// grid (S/128, H, B), 128 threads; thread t owns query q0+t.
// Writes y as pre-tiled fp16 hi/lo (kchunk == head).
__global__ __launch_bounds__(128) void attn_kernel() {
    __shared__ float Ks[64][64];
    __shared__ float Vs[64][64];
    const int t  = threadIdx.x;
    const int q0 = blockIdx.x << 7;
    const int h  = blockIdx.y;
    const int b  = blockIdx.z;
    const size_t bh = (size_t)(b * H_ + h) * S_;
    const int sq = q0 + t;

    float qreg[64];
    {
        const float4* qp = (const float4*)(g_q + ((bh + sq) << 6));
        #pragma unroll
        for (int u = 0; u < 16; ++u) {
            float4 v = qp[u];
            qreg[u*4+0] = v.x * 0.125f;
            qreg[u*4+1] = v.y * 0.125f;
            qreg[u*4+2] = v.z * 0.125f;
            qreg[u*4+3] = v.w * 0.125f;
        }
    }

    float m = -1e30f, l = 0.f;
    float o[64];
    #pragma unroll
    for (int d = 0; d < 64; ++d) o[d] = 0.f;

    const int kt0 = (q0 >= WIN_) ? ((q0 - WIN_ + 1) >> 6) : 0;
    const int kt1 = (q0 + 127) >> 6;

    for (int kt = kt0; kt <= kt1; ++kt) {
        const int jb = kt << 6;
        __syncthreads();
        #pragma unroll
        for (int u = 0; u < 8; ++u) {
            int f4  = t + (u << 7);
            int row = f4 >> 4;
            int c4  = (f4 & 15) << 2;
            *(float4*)&Ks[row][c4] = *(const float4*)(g_k + ((bh + jb + row) << 6) + c4);
            *(float4*)&Vs[row][c4] = *(const float4*)(g_v + ((bh + jb + row) << 6) + c4);
        }
        __syncthreads();

        for (int js = 0; js < 64; js += 16) {
            float sc[16];
            float mx = -1e30f;
            #pragma unroll
            for (int jj = 0; jj < 16; ++jj) {
                int jpos = jb + js + jj;
                float dot = 0.f;
                #pragma unroll
                for (int d = 0; d < 64; ++d)
                    dot += qreg[d] * Ks[js + jj][d];
                bool ok = (jpos <= sq) && (sq - jpos < WIN_);
                sc[jj] = ok ? dot : -1e30f;
                mx = fmaxf(mx, sc[jj]);
            }
            if (mx > -1e29f) {
                float mnew  = fmaxf(m, mx);
                float alpha = __expf(m - mnew);
                l *= alpha;
                #pragma unroll
                for (int d = 0; d < 64; ++d) o[d] *= alpha;
                #pragma unroll
                for (int jj = 0; jj < 16; ++jj) {
                    float p = __expf(sc[jj] - mnew);
                    l += p;
                    #pragma unroll
                    for (int d = 0; d < 64; ++d)
                        o[d] += p * Vs[js + jj][d];
                }
                m = mnew;
            }
        }
    }

    float inv = 1.f / l;
    const int mrow = b * S_ + sq;
    const size_t rbase = (((size_t)h * M_TOTAL + mrow) << 6);
    #pragma unroll
    for (int d = 0; d < 64; ++d) {
        float val = o[d] * inv;
        __half hh = __float2half_rn(val);
        __half ll = __float2half_rn(val - __half2float(hh));
        size_t idx = rbase + ((((d >> 3) ^ (mrow & 7)) << 3) | (d & 7));
        g_yh[idx] = hh;
        g_yl[idx] = ll;
    }
}

// ---------------- launch ----------------
extern "C" void kernel_launch(void* const* d_in, const int* in_sizes, int n_in,
                              void* d_out, int out_size)
{
    const float* x  = (const float*)d_in[0];
    const float* Wq = (const float*)d_in[1];
    const float* Wk = (const float*)d_in[2];
    const float* Wv = (const float*)d_in[3];
    const float* Wo = (const float*)d_in[4];
    float* out = (float*)d_out;

    cudaFuncSetAttribute(gemm_f16_kernel,
                         cudaFuncAttributeMaxDynamicSharedMemorySize, SMEM_BYTES);

    rope_table_kernel<<<(S_ * 32 + 255) / 256, 256>>>();
    conv_x_kernel<<<(M_TOTAL * E_) / 256, 256>>>(x);
    conv_w_kernel<<<(4 * E_ * E_) / 256, 256>>>(Wq, Wk, Wv, Wo);

    dim3 g1(E_ / 128, M_TOTAL / 128, 3);   // (8, 32, 3)
    gemm_f16_kernel<<<g1, 256, SMEM_BYTES>>>(1, nullptr);

    dim3 ga(S_ / 128, H_, B_);
    attn_kernel<<<ga, 128>>>();

    dim3 g2(E_ / 128, M_TOTAL / 128, 1);
    gemm_f16_kernel<<<g2, 256, SMEM_BYTES>>>(0, out);
}

// round 4
// speedup vs baseline: 3.5126x; 1.6425x over previous
#include <cuda_runtime.h>
#include <cuda_fp16.h>
#include <math.h>
#include <stdint.h>

#define B_ 2
#define S_ 2048
#define E_ 1024
#define H_ 16
#define D_ 64
#define WIN_ 256
#define M_TOTAL (B_*S_)          // 4096
#define NCH 16                    // K chunks of 64

// ---------------- scratch (device globals, allocation-free) ----------------
// GEMM operands: [kchunk 16][row 4096][64], 16B-chunk swizzled by (row&7)
__device__ __align__(1024) __half g_xh[NCH*M_TOTAL*64];
__device__ __align__(1024) __half g_xl[NCH*M_TOTAL*64];
__device__ __align__(1024) __half g_wh[4*NCH*E_*64];
__device__ __align__(1024) __half g_wl[4*NCH*E_*64];
__device__ __align__(1024) __half g_yh[NCH*M_TOTAL*64];
__device__ __align__(1024) __half g_yl[NCH*M_TOTAL*64];
// attention operands (fp16 hi/lo, swizzled tiles):
// Q: [bh 32][qtile 16][128][64]   K/V: [bh 32][ktile 32][64][64]
__device__ __align__(1024) __half g_qf_h[B_*H_*S_*64];
__device__ __align__(1024) __half g_qf_l[B_*H_*S_*64];
__device__ __align__(1024) __half g_kf_h[B_*H_*S_*64];
__device__ __align__(1024) __half g_kf_l[B_*H_*S_*64];
__device__ __align__(1024) __half g_vf_h[B_*H_*S_*64];
__device__ __align__(1024) __half g_vf_l[B_*H_*S_*64];
__device__ float g_cos[S_*32];
__device__ float g_sin[S_*32];

// ---------------- PTX helpers ----------------
__device__ __forceinline__ uint32_t smem_u32(const void* p) {
    uint32_t a;
    asm("{ .reg .u64 t; cvta.to.shared.u64 t, %1; cvt.u32.u64 %0, t; }"
        : "=r"(a) : "l"(p));
    return a;
}

__device__ __forceinline__ void mbar_wait(uint32_t mbar, uint32_t parity) {
    asm volatile(
        "{\n\t.reg .pred P;\n\t"
        "WL%=:\n\t"
        "mbarrier.try_wait.parity.acquire.cta.shared::cta.b64 P, [%0], %1, 0x989680;\n\t"
        "@P bra WD%=;\n\t"
        "bra WL%=;\n\t"
        "WD%=:\n\t}"
        :: "r"(mbar), "r"(parity) : "memory");
}

__device__ __forceinline__ void bulk_cp(uint32_t dst, const void* src, uint32_t bytes,
                                        uint32_t mbar) {
    asm volatile(
        "cp.async.bulk.shared::cluster.global.mbarrier::complete_tx::bytes [%0], [%1], %2, [%3];"
        :: "r"(dst), "l"(src), "r"(bytes), "r"(mbar) : "memory");
}

#define LDSM4(r, a) \
    asm volatile("ldmatrix.sync.aligned.m8n8.x4.shared.b16 {%0,%1,%2,%3}, [%4];" \
        : "=r"((r)[0]), "=r"((r)[1]), "=r"((r)[2]), "=r"((r)[3]) : "r"(a))

#define LDSM4T(r, a) \
    asm volatile("ldmatrix.sync.aligned.m8n8.x4.trans.shared.b16 {%0,%1,%2,%3}, [%4];" \
        : "=r"((r)[0]), "=r"((r)[1]), "=r"((r)[2]), "=r"((r)[3]) : "r"(a))

#define MMA16816(c, a, b) \
    asm volatile("mma.sync.aligned.m16n8k16.row.col.f32.f16.f16.f32 " \
        "{%0,%1,%2,%3}, {%4,%5,%6,%7}, {%8,%9}, {%0,%1,%2,%3};" \
        : "+f"((c)[0]), "+f"((c)[1]), "+f"((c)[2]), "+f"((c)[3]) \
        : "r"((a)[0]), "r"((a)[1]), "r"((a)[2]), "r"((a)[3]), \
          "r"((b)[0]), "r"((b)[1]))

// fp32 pair -> fp16 hi/lo half2 (bit-packed)
__device__ __forceinline__ uint32_t pack_hl(float a, float b, uint32_t& lo) {
    __half2 h = __floats2half2_rn(a, b);
    float2 bk = __half22float2(h);
    __half2 l = __floats2half2_rn(a - bk.x, b - bk.y);
    lo = *(uint32_t*)&l;
    return *(uint32_t*)&h;
}

// ---------------- RoPE table ----------------
__global__ void rope_table_kernel() {
    int i = blockIdx.x * blockDim.x + threadIdx.x;
    if (i >= S_ * 32) return;
    int s = i >> 5, j = i & 31;
    double invf = pow(10000.0, -(double)j / 32.0);
    double ang  = (double)s * invf;
    g_cos[i] = (float)cos(ang);
    g_sin[i] = (float)sin(ang);
}

// ---------------- fp32 -> pre-tiled pre-swizzled fp16 hi/lo ----------------
__global__ void conv_x_kernel(const float* __restrict__ x) {
    int i = blockIdx.x * blockDim.x + threadIdx.x;
    if (i >= M_TOTAL * E_) return;
    int m = i >> 10, k = i & 1023;
    float v = x[i];
    __half h = __float2half_rn(v);
    __half l = __float2half_rn(v - __half2float(h));
    int k63 = k & 63;
    size_t idx = (((size_t)(k >> 6) * M_TOTAL + m) << 6)
               + ((((k63 >> 3) ^ (m & 7)) << 3) | (k63 & 7));
    g_xh[idx] = h; g_xl[idx] = l;
}

__global__ void conv_w_kernel(const float* __restrict__ Wq, const float* __restrict__ Wk,
                              const float* __restrict__ Wv, const float* __restrict__ Wo) {
    int i = blockIdx.x * blockDim.x + threadIdx.x;
    if (i >= 4 * E_ * E_) return;
    int z = i >> 20;
    int j = i & (E_ * E_ - 1);
    int n = j >> 10, k = j & 1023;
    const float* p = (z == 0) ? Wq : (z == 1) ? Wk : (z == 2) ? Wv : Wo;
    float v = p[j];
    __half h = __float2half_rn(v);
    __half l = __float2half_rn(v - __half2float(h));
    int c = (k >> 3) & 7, w = k & 7;
    size_t idx = ((((size_t)z * NCH + (k >> 6)) * E_ + n) << 6)
               + (((c ^ (n & 7)) << 3) | w);
    g_wh[idx] = h; g_wl[idx] = l;
}

// ---------------- HMMA fp16-split GEMM: C = A @ W^T ----------------
#define TILE_A 16384
#define STAGE_B 65536
#define SMEM_BYTES (1024 + 2*STAGE_B)

__global__ __launch_bounds__(256) void gemm_f16_kernel(int mode, float* __restrict__ Cout)
{
    extern __shared__ char smraw[];
    const uint32_t raw = smem_u32(smraw);
    const uint32_t HDR = (raw + 1023) & ~1023u;
    const uint32_t TIL = HDR + 1024;

    const int tid  = threadIdx.x;
    const int lane = tid & 31;
    const int wid  = tid >> 5;
    const int wm   = wid & 3;
    const int wn   = wid >> 2;
    const int sub  = lane >> 3;
    const int n0 = blockIdx.x << 7;
    const int m0 = blockIdx.y << 7;
    const int z  = (mode == 1) ? (int)blockIdx.z : 3;

    const __half* __restrict__ Ah = (mode == 1) ? g_xh : g_yh;
    const __half* __restrict__ Al = (mode == 1) ? g_xl : g_yl;

    if (tid == 0) {
        asm volatile("mbarrier.init.shared.b64 [%0], %1;" :: "r"(HDR),     "r"(1u) : "memory");
        asm volatile("mbarrier.init.shared.b64 [%0], %1;" :: "r"(HDR + 8), "r"(1u) : "memory");
    }
    __syncthreads();

    float acc[2][8][4];
    #pragma unroll
    for (int mi = 0; mi < 2; ++mi)
        #pragma unroll
        for (int ng = 0; ng < 8; ++ng)
            #pragma unroll
            for (int j = 0; j < 4; ++j) acc[mi][ng][j] = 0.f;

    auto issue = [&](int ci, int st) {
        uint32_t mb = HDR + st * 8;
        uint32_t db = TIL + st * STAGE_B;
        asm volatile("mbarrier.arrive.expect_tx.shared.b64 _, [%0], %1;"
                     :: "r"(mb), "r"((uint32_t)STAGE_B) : "memory");
        bulk_cp(db,              Ah   + (((size_t)ci * M_TOTAL + m0) << 6), TILE_A, mb);
        bulk_cp(db + TILE_A,     Al   + (((size_t)ci * M_TOTAL + m0) << 6), TILE_A, mb);
        bulk_cp(db + 2 * TILE_A, g_wh + ((((size_t)z * NCH + ci) * E_ + n0) << 6), TILE_A, mb);
        bulk_cp(db + 3 * TILE_A, g_wl + ((((size_t)z * NCH + ci) * E_ + n0) << 6), TILE_A, mb);
    };

    if (tid == 0) issue(0, 0);

    for (int i = 0; i < NCH; ++i) {
        if (i + 1 < NCH && tid == 0) issue(i + 1, (i + 1) & 1);
        const int st = i & 1;
        mbar_wait(HDR + st * 8, (uint32_t)((i >> 1) & 1));
        const uint32_t base = TIL + st * STAGE_B;

        #pragma unroll
        for (int ks = 0; ks < 4; ++ks) {
            uint32_t Af[2][2][4];
            {
                const int ar0 = wm * 32 + (lane & 7) + ((sub & 1) << 3);
                const int akc = ks * 2 + (sub >> 1);
                #pragma unroll
                for (int mi = 0; mi < 2; ++mi) {
                    int r = ar0 + mi * 16;
                    uint32_t off = (uint32_t)(r * 128 + ((akc ^ (r & 7)) << 4));
                    LDSM4(Af[0][mi], base + off);
                    LDSM4(Af[1][mi], base + TILE_A + off);
                }
            }
            uint32_t Bf[2][4][4];
            {
                const int br0 = wn * 64 + (lane & 7) + ((sub >> 1) << 3);
                const int bkc = ks * 2 + (sub & 1);
                #pragma unroll
                for (int g = 0; g < 4; ++g) {
                    int r = br0 + g * 16;
                    uint32_t off = (uint32_t)(r * 128 + ((bkc ^ (r & 7)) << 4));
                    LDSM4(Bf[0][g], base + 2 * TILE_A + off);
                    LDSM4(Bf[1][g], base + 3 * TILE_A + off);
                }
            }
            #pragma unroll
            for (int mi = 0; mi < 2; ++mi)
                #pragma unroll
                for (int ng = 0; ng < 8; ++ng) {
                    const int g = ng >> 1, o = (ng & 1) << 1;
                    MMA16816(acc[mi][ng], Af[0][mi], &Bf[0][g][o]);   // hh
                    MMA16816(acc[mi][ng], Af[0][mi], &Bf[1][g][o]);   // h*l
                    MMA16816(acc[mi][ng], Af[1][mi], &Bf[0][g][o]);   // l*h
                }
        }
        __syncthreads();
    }

    // ---- epilogue ----
    const int col2 = (lane & 3) << 1;
    const int h = (n0 >> 6) + wn;
    #pragma unroll
    for (int mi = 0; mi < 2; ++mi) {
        #pragma unroll
        for (int rr = 0; rr < 2; ++rr) {
            const int m = m0 + wm * 32 + mi * 16 + rr * 8 + (lane >> 2);
            if (mode == 0) {
                float* dp = Cout + (size_t)m * E_ + n0 + wn * 64;
                #pragma unroll
                for (int ng = 0; ng < 8; ++ng) {
                    float2 v = make_float2(acc[mi][ng][rr * 2], acc[mi][ng][rr * 2 + 1]);
                    *(float2*)(dp + ng * 8 + col2) = v;
                }
            } else {
                const int bb = m >> 11, ss = m & (S_ - 1);
                const int rsw = ss & 7;
                if (z == 2) {
                    // V: [bh][ktile][64][64]
                    size_t base = ((((size_t)(bb * H_ + h) * (S_ / 64) + (ss >> 6)) * 64
                                    + (ss & 63)) << 6);
                    #pragma unroll
                    for (int ng = 0; ng < 8; ++ng) {
                        int d = ng * 8 + col2;
                        uint32_t lo, hi = pack_hl(acc[mi][ng][rr*2], acc[mi][ng][rr*2+1], lo);
                        size_t idx = base + ((((d >> 3) ^ rsw) << 3) | (d & 7));
                        *(uint32_t*)&g_vf_h[idx] = hi;
                        *(uint32_t*)&g_vf_l[idx] = lo;
                    }
                } else {
                    // Q/K: RoPE (+ Q scale)
                    float r1[4][2], r2[4][2];
                    #pragma unroll
                    for (int ng = 0; ng < 4; ++ng)
                        #pragma unroll
                        for (int jj = 0; jj < 2; ++jj) {
                            const int d = ng * 8 + col2 + jj;
                            float x1 = acc[mi][ng][rr * 2 + jj];
                            float x2 = acc[mi][ng + 4][rr * 2 + jj];
                            float c  = g_cos[(ss << 5) + d];
                            float sn = g_sin[(ss << 5) + d];
                            float v1 = x1 * c - x2 * sn;
                            float v2 = x2 * c + x1 * sn;
                            if (z == 0) { v1 *= 0.125f; v2 *= 0.125f; }
                            r1[ng][jj] = v1; r2[ng][jj] = v2;
                        }
                    size_t base;
                    __half *ph, *pl;
                    if (z == 0) {
                        base = ((((size_t)(bb * H_ + h) * (S_ / 128) + (ss >> 7)) * 128
                                 + (ss & 127)) << 6);
                        ph = g_qf_h; pl = g_qf_l;
                    } else {
                        base = ((((size_t)(bb * H_ + h) * (S_ / 64) + (ss >> 6)) * 64
                                 + (ss & 63)) << 6);
                        ph = g_kf_h; pl = g_kf_l;
                    }
                    #pragma unroll
                    for (int ng = 0; ng < 4; ++ng) {
                        int d = ng * 8 + col2;
                        uint32_t lo, hi = pack_hl(r1[ng][0], r1[ng][1], lo);
                        size_t idx = base + ((((d >> 3) ^ rsw) << 3) | (d & 7));
                        *(uint32_t*)&ph[idx] = hi;
                        *(uint32_t*)&pl[idx] = lo;
                        int d2 = d + 32;
                        uint32_t lo2, hi2 = pack_hl(r2[ng][0], r2[ng][1], lo2);
                        size_t idx2 = base + ((((d2 >> 3) ^ rsw) << 3) | (d2 & 7));
                        *(uint32_t*)&ph[idx2] = hi2;
                        *(uint32_t*)&pl[idx2] = lo2;
                    }
                }
            }
        }
    }
}

// ---------------- HMMA windowed flash attention ----------------
// grid (S/128, H, B), 256 threads (8 warps x 16 query rows).
#define Q_BYTES   16384
#define KV_TILE   8192
#define KV_STAGE  32768
#define SMEM_ATTN (1024 + 2*Q_BYTES + 2*KV_STAGE)

__global__ __launch_bounds__(256) void attn_kernel() {
    extern __shared__ char smraw[];
    const uint32_t raw = smem_u32(smraw);
    const uint32_t HDR  = (raw + 1023) & ~1023u;
    const uint32_t TILQ = HDR + 1024;
    const uint32_t KVB  = TILQ + 2 * Q_BYTES;

    const int tid  = threadIdx.x;
    const int lane = tid & 31;
    const int wid  = tid >> 5;
    const int sub  = lane >> 3;
    const int g    = lane >> 2;         // row-in-16 (0..7)
    const int t2   = (lane & 3) << 1;   // col pair base
    const int qt = blockIdx.x;
    const int q0 = qt << 7;
    const int h  = blockIdx.y;
    const int b  = blockIdx.z;
    const int bh = b * H_ + h;
    const int wrow = wid * 16;

    if (tid == 0) {
        asm volatile("mbarrier.init.shared.b64 [%0], %1;" :: "r"(HDR),      "r"(1u) : "memory");
        asm volatile("mbarrier.init.shared.b64 [%0], %1;" :: "r"(HDR + 8),  "r"(1u) : "memory");
        asm volatile("mbarrier.init.shared.b64 [%0], %1;" :: "r"(HDR + 16), "r"(1u) : "memory");
    }
    __syncthreads();

    const int kt0 = (q0 >= WIN_) ? ((q0 - WIN_ + 1) >> 6) : 0;
    const int kt1 = (q0 + 127) >> 6;
    const int nt  = kt1 - kt0 + 1;

    auto issueKV = [&](int kt, int j) {
        int st = j & 1;
        uint32_t mb = HDR + 8 + st * 8;
        uint32_t db = KVB + st * KV_STAGE;
        asm volatile("mbarrier.arrive.expect_tx.shared.b64 _, [%0], %1;"
                     :: "r"(mb), "r"((uint32_t)KV_STAGE) : "memory");
        const size_t tb = ((size_t)bh * (S_ / 64) + kt) << 12;   // *4096 halves
        bulk_cp(db,               g_kf_h + tb, KV_TILE, mb);
        bulk_cp(db + KV_TILE,     g_kf_l + tb, KV_TILE, mb);
        bulk_cp(db + 2 * KV_TILE, g_vf_h + tb, KV_TILE, mb);
        bulk_cp(db + 3 * KV_TILE, g_vf_l + tb, KV_TILE, mb);
    };

    if (tid == 0) {
        asm volatile("mbarrier.arrive.expect_tx.shared.b64 _, [%0], %1;"
                     :: "r"(HDR), "r"((uint32_t)(2 * Q_BYTES)) : "memory");
        const size_t qb = ((size_t)bh * (S_ / 128) + qt) << 13;  // *8192 halves
        bulk_cp(TILQ,           g_qf_h + qb, Q_BYTES, HDR);
        bulk_cp(TILQ + Q_BYTES, g_qf_l + qb, Q_BYTES, HDR);
        issueKV(kt0, 0);
        if (nt > 1) issueKV(kt0 + 1, 1);
    }

    // Q fragments (held all loop)
    uint32_t Aqh[4][4], Aql[4][4];
    mbar_wait(HDR, 0u);
    {
        const int r = wrow + (lane & 7) + ((sub & 1) << 3);
        #pragma unroll
        for (int ks = 0; ks < 4; ++ks) {
            uint32_t off = (uint32_t)(r * 128 + (((ks * 2 + (sub >> 1)) ^ (r & 7)) << 4));
            LDSM4(Aqh[ks], TILQ + off);
            LDSM4(Aql[ks], TILQ + Q_BYTES + off);
        }
    }

    float oacc[8][4];
    #pragma unroll
    for (int dg = 0; dg < 8; ++dg)
        #pragma unroll
        for (int j = 0; j < 4; ++j) oacc[dg][j] = 0.f;
    float mrow[2] = {-1e30f, -1e30f};
    float lrow[2] = {0.f, 0.f};
    const int sq0 = q0 + wrow + g;

    for (int j = 0; j < nt; ++j) {
        const int jb = (kt0 + j) << 6;
        const int st = j & 1;
        mbar_wait(HDR + 8 + st * 8, (uint32_t)((j >> 1) & 1));
        const uint32_t kb_h = KVB + st * KV_STAGE;
        const uint32_t kb_l = kb_h + KV_TILE;
        const uint32_t vb_h = kb_h + 2 * KV_TILE;
        const uint32_t vb_l = kb_h + 3 * KV_TILE;

        // ---- S = Q K^T (hi/lo split) ----
        float sacc[8][4];
        #pragma unroll
        for (int cg = 0; cg < 8; ++cg)
            #pragma unroll
            for (int jj = 0; jj < 4; ++jj) sacc[cg][jj] = 0.f;

        #pragma unroll
        for (int ks = 0; ks < 4; ++ks) {
            #pragma unroll
            for (int kg = 0; kg < 4; ++kg) {
                uint32_t Bh[4], Bl[4];
                const int r = kg * 16 + (lane & 7) + ((sub >> 1) << 3);
                uint32_t off = (uint32_t)(r * 128 + (((ks * 2 + (sub & 1)) ^ (r & 7)) << 4));
                LDSM4(Bh, kb_h + off);
                LDSM4(Bl, kb_l + off);
                MMA16816(sacc[kg*2],   Aqh[ks], &Bh[0]);
                MMA16816(sacc[kg*2],   Aqh[ks], &Bl[0]);
                MMA16816(sacc[kg*2],   Aql[ks], &Bh[0]);
                MMA16816(sacc[kg*2+1], Aqh[ks], &Bh[2]);
                MMA16816(sacc[kg*2+1], Aqh[ks], &Bl[2]);
                MMA16816(sacc[kg*2+1], Aql[ks], &Bh[2]);
            }
        }

        // ---- mask + online softmax ----
        float mx[2] = {-1e30f, -1e30f};
        #pragma unroll
        for (int cg = 0; cg < 8; ++cg) {
            const int jp = jb + cg * 8 + t2;
            #pragma unroll
            for (int rh = 0; rh < 2; ++rh) {
                const int sq = sq0 + rh * 8;
                #pragma unroll
                for (int jj = 0; jj < 2; ++jj) {
                    float& s = sacc[cg][rh * 2 + jj];
                    const int jpos = jp + jj;
                    bool ok = (jpos <= sq) && (sq - jpos < WIN_);
                    if (!ok) s = -1e30f;
                    mx[rh] = fmaxf(mx[rh], s);
                }
            }
        }
        #pragma unroll
        for (int off = 1; off < 4; off <<= 1) {
            mx[0] = fmaxf(mx[0], __shfl_xor_sync(0xFFFFFFFFu, mx[0], off));
            mx[1] = fmaxf(mx[1], __shfl_xor_sync(0xFFFFFFFFu, mx[1], off));
        }
        float mn[2], al[2], safe[2];
        #pragma unroll
        for (int rh = 0; rh < 2; ++rh) {
            mn[rh]   = fmaxf(mrow[rh], mx[rh]);
            al[rh]   = __expf(mrow[rh] - mn[rh]);
            safe[rh] = (mn[rh] < -1e29f) ? 0.f : mn[rh];
            mrow[rh] = mn[rh];
            lrow[rh] *= al[rh];
        }
        #pragma unroll
        for (int cg = 0; cg < 8; ++cg)
            #pragma unroll
            for (int rh = 0; rh < 2; ++rh)
                #pragma unroll
                for (int jj = 0; jj < 2; ++jj) {
                    float p = __expf(sacc[cg][rh * 2 + jj] - safe[rh]);
                    sacc[cg][rh * 2 + jj] = p;
                    lrow[rh] += p;
                }
        #pragma unroll
        for (int dg = 0; dg < 8; ++dg) {
            oacc[dg][0] *= al[0]; oacc[dg][1] *= al[0];
            oacc[dg][2] *= al[1]; oacc[dg][3] *= al[1];
        }

        // ---- O += P V (hi/lo split) ----
        #pragma unroll
        for (int kc4 = 0; kc4 < 4; ++kc4) {
            uint32_t ph[4], pl[4];
            ph[0] = pack_hl(sacc[kc4*2][0],   sacc[kc4*2][1],   pl[0]);
            ph[1] = pack_hl(sacc[kc4*2][2],   sacc[kc4*2][3],   pl[1]);
            ph[2] = pack_hl(sacc[kc4*2+1][0], sacc[kc4*2+1][1], pl[2]);
            ph[3] = pack_hl(sacc[kc4*2+1][2], sacc[kc4*2+1][3], pl[3]);
            const int r = kc4 * 16 + (lane & 7) + ((sub & 1) << 3);
            #pragma unroll
            for (int dg4 = 0; dg4 < 4; ++dg4) {
                uint32_t Vh[4], Vl[4];
                uint32_t off = (uint32_t)(r * 128 + (((dg4 * 2 + (sub >> 1)) ^ (r & 7)) << 4));
                LDSM4T(Vh, vb_h + off);
                LDSM4T(Vl, vb_l + off);
                MMA16816(oacc[dg4*2],   ph, &Vh[0]);
                MMA16816(oacc[dg4*2],   ph, &Vl[0]);
                MMA16816(oacc[dg4*2],   pl, &Vh[0]);
                MMA16816(oacc[dg4*2+1], ph, &Vh[2]);
                MMA16816(oacc[dg4*2+1], ph, &Vl[2]);
                MMA16816(oacc[dg4*2+1], pl, &Vh[2]);
            }
        }

        __syncthreads();
        if (tid == 0 && j + 2 < nt) issueKV(kt0 + j + 2, j + 2);
    }

    // ---- finalize: quad-reduce l, normalize, write y (gemm hi/lo layout) ----
    #pragma unroll
    for (int off = 1; off < 4; off <<= 1) {
        lrow[0] += __shfl_xor_sync(0xFFFFFFFFu, lrow[0], off);
        lrow[1] += __shfl_xor_sync(0xFFFFFFFFu, lrow[1], off);
    }
    float inv[2] = {1.f / lrow[0], 1.f / lrow[1]};
    #pragma unroll
    for (int rh = 0; rh < 2; ++rh) {
        const int m = b * S_ + sq0 + rh * 8;
        const size_t base = ((size_t)h * M_TOTAL + m) << 6;
        const int rsw = m & 7;
        #pragma unroll
        for (int dg = 0; dg < 8; ++dg) {
            int d = dg * 8 + t2;
            float v0 = oacc[dg][rh * 2]     * inv[rh];
            float v1 = oacc[dg][rh * 2 + 1] * inv[rh];
            uint32_t lo, hi = pack_hl(v0, v1, lo);
            size_t idx = base + (((dg ^ rsw) << 3) | (d & 7));
            *(uint32_t*)&g_yh[idx] = hi;
            *(uint32_t*)&g_yl[idx] = lo;
        }
    }
}

// ---------------- launch ----------------
extern "C" void kernel_launch(void* const* d_in, const int* in_sizes, int n_in,
                              void* d_out, int out_size)
{
    const float* x  = (const float*)d_in[0];
    const float* Wq = (const float*)d_in[1];
    const float* Wk = (const float*)d_in[2];
    const float* Wv = (const float*)d_in[3];
    const float* Wo = (const float*)d_in[4];
    float* out = (float*)d_out;

    cudaFuncSetAttribute(gemm_f16_kernel,
                         cudaFuncAttributeMaxDynamicSharedMemorySize, SMEM_BYTES);
    cudaFuncSetAttribute(attn_kernel,
                         cudaFuncAttributeMaxDynamicSharedMemorySize, SMEM_ATTN);

    rope_table_kernel<<<(S_ * 32 + 255) / 256, 256>>>();
    conv_x_kernel<<<(M_TOTAL * E_) / 256, 256>>>(x);
    conv_w_kernel<<<(4 * E_ * E_) / 256, 256>>>(Wq, Wk, Wv, Wo);

    dim3 g1(E_ / 128, M_TOTAL / 128, 3);   // (8, 32, 3)
    gemm_f16_kernel<<<g1, 256, SMEM_BYTES>>>(1, nullptr);

    dim3 ga(S_ / 128, H_, B_);
    attn_kernel<<<ga, 256, SMEM_ATTN>>>();

    dim3 g2(E_ / 128, M_TOTAL / 128, 1);
    gemm_f16_kernel<<<g2, 256, SMEM_BYTES>>>(0, out);
}

// round 5
// speedup vs baseline: 3.6104x; 1.0278x over previous
#include <cuda_runtime.h>
#include <cuda_fp16.h>
#include <math.h>
#include <stdint.h>

#define B_ 2
#define S_ 2048
#define E_ 1024
#define H_ 16
#define D_ 64
#define WIN_ 256
#define M_TOTAL (B_*S_)          // 4096
#define NCH 16                    // K chunks of 64

// ---------------- scratch (device globals, allocation-free) ----------------
// GEMM operands: [kchunk 16][row 4096][64], 16B-chunk swizzled by (row&7)
__device__ __align__(1024) __half g_xh[NCH*M_TOTAL*64];
__device__ __align__(1024) __half g_xl[NCH*M_TOTAL*64];
__device__ __align__(1024) __half g_wh[4*NCH*E_*64];
__device__ __align__(1024) __half g_wl[4*NCH*E_*64];
__device__ __align__(1024) __half g_yh[NCH*M_TOTAL*64];
__device__ __align__(1024) __half g_yl[NCH*M_TOTAL*64];
// attention operands (fp16 hi/lo, swizzled tiles):
// Q: [bh 32][qtile 16][128][64]   K/V: [bh 32][ktile 32][64][64]
__device__ __align__(1024) __half g_qf_h[B_*H_*S_*64];
__device__ __align__(1024) __half g_qf_l[B_*H_*S_*64];
__device__ __align__(1024) __half g_kf_h[B_*H_*S_*64];
__device__ __align__(1024) __half g_kf_l[B_*H_*S_*64];
__device__ __align__(1024) __half g_vf_h[B_*H_*S_*64];
__device__ __align__(1024) __half g_vf_l[B_*H_*S_*64];
__device__ float g_cos[S_*32];
__device__ float g_sin[S_*32];

// ---------------- PTX helpers ----------------
__device__ __forceinline__ uint32_t smem_u32(const void* p) {
    uint32_t a;
    asm("{ .reg .u64 t; cvta.to.shared.u64 t, %1; cvt.u32.u64 %0, t; }"
        : "=r"(a) : "l"(p));
    return a;
}

__device__ __forceinline__ void mbar_wait(uint32_t mbar, uint32_t parity) {
    asm volatile(
        "{\n\t.reg .pred P;\n\t"
        "WL%=:\n\t"
        "mbarrier.try_wait.parity.acquire.cta.shared::cta.b64 P, [%0], %1, 0x989680;\n\t"
        "@P bra WD%=;\n\t"
        "bra WL%=;\n\t"
        "WD%=:\n\t}"
        :: "r"(mbar), "r"(parity) : "memory");
}

__device__ __forceinline__ void bulk_cp(uint32_t dst, const void* src, uint32_t bytes,
                                        uint32_t mbar) {
    asm volatile(
        "cp.async.bulk.shared::cluster.global.mbarrier::complete_tx::bytes [%0], [%1], %2, [%3];"
        :: "r"(dst), "l"(src), "r"(bytes), "r"(mbar) : "memory");
}

#define LDSM4(r, a) \
    asm volatile("ldmatrix.sync.aligned.m8n8.x4.shared.b16 {%0,%1,%2,%3}, [%4];" \
        : "=r"((r)[0]), "=r"((r)[1]), "=r"((r)[2]), "=r"((r)[3]) : "r"(a))

#define LDSM4T(r, a) \
    asm volatile("ldmatrix.sync.aligned.m8n8.x4.trans.shared.b16 {%0,%1,%2,%3}, [%4];" \
        : "=r"((r)[0]), "=r"((r)[1]), "=r"((r)[2]), "=r"((r)[3]) : "r"(a))

#define MMA16816(c, a, b) \
    asm volatile("mma.sync.aligned.m16n8k16.row.col.f32.f16.f16.f32 " \
        "{%0,%1,%2,%3}, {%4,%5,%6,%7}, {%8,%9}, {%0,%1,%2,%3};" \
        : "+f"((c)[0]), "+f"((c)[1]), "+f"((c)[2]), "+f"((c)[3]) \
        : "r"((a)[0]), "r"((a)[1]), "r"((a)[2]), "r"((a)[3]), \
          "r"((b)[0]), "r"((b)[1]))

// fp32 pair -> fp16 hi/lo half2 (bit-packed)
__device__ __forceinline__ uint32_t pack_hl(float a, float b, uint32_t& lo) {
    __half2 h = __floats2half2_rn(a, b);
    float2 bk = __half22float2(h);
    __half2 l = __floats2half2_rn(a - bk.x, b - bk.y);
    lo = *(uint32_t*)&l;
    return *(uint32_t*)&h;
}

// ---------------- RoPE table ----------------
__global__ void rope_table_kernel() {
    int i = blockIdx.x * blockDim.x + threadIdx.x;
    if (i >= S_ * 32) return;
    int s = i >> 5, j = i & 31;
    double invf = pow(10000.0, -(double)j / 32.0);
    double ang  = (double)s * invf;
    g_cos[i] = (float)cos(ang);
    g_sin[i] = (float)sin(ang);
}

// ---------------- fp32 -> pre-tiled pre-swizzled fp16 hi/lo ----------------
__global__ void conv_x_kernel(const float* __restrict__ x) {
    int i = blockIdx.x * blockDim.x + threadIdx.x;
    if (i >= M_TOTAL * E_) return;
    int m = i >> 10, k = i & 1023;
    float v = x[i];
    __half h = __float2half_rn(v);
    __half l = __float2half_rn(v - __half2float(h));
    int k63 = k & 63;
    size_t idx = (((size_t)(k >> 6) * M_TOTAL + m) << 6)
               + ((((k63 >> 3) ^ (m & 7)) << 3) | (k63 & 7));
    g_xh[idx] = h; g_xl[idx] = l;
}

__global__ void conv_w_kernel(const float* __restrict__ Wq, const float* __restrict__ Wk,
                              const float* __restrict__ Wv, const float* __restrict__ Wo) {
    int i = blockIdx.x * blockDim.x + threadIdx.x;
    if (i >= 4 * E_ * E_) return;
    int z = i >> 20;
    int j = i & (E_ * E_ - 1);
    int n = j >> 10, k = j & 1023;
    const float* p = (z == 0) ? Wq : (z == 1) ? Wk : (z == 2) ? Wv : Wo;
    float v = p[j];
    __half h = __float2half_rn(v);
    __half l = __float2half_rn(v - __half2float(h));
    int c = (k >> 3) & 7, w = k & 7;
    size_t idx = ((((size_t)z * NCH + (k >> 6)) * E_ + n) << 6)
               + (((c ^ (n & 7)) << 3) | w);
    g_wh[idx] = h; g_wl[idx] = l;
}

// ---------------- HMMA fp16-split GEMM: C = A @ W^T ----------------
// CTA tile 256x128, 8 warps (4M x 2N), warp tile 64x64, K chunks of 64.
#define TILE_AH 32768                       // 256 rows x 64 halves x 2B
#define TILE_BH 16384                       // 128 rows x 64 halves x 2B
#define STAGE_B (2*TILE_AH + 2*TILE_BH)     // 96 KB
#define SMEM_BYTES (1024 + 2*STAGE_B)       // ~193 KB

__global__ __launch_bounds__(256) void gemm_f16_kernel(int mode, float* __restrict__ Cout)
{
    extern __shared__ char smraw[];
    const uint32_t raw = smem_u32(smraw);
    const uint32_t HDR = (raw + 1023) & ~1023u;
    const uint32_t TIL = HDR + 1024;

    const int tid  = threadIdx.x;
    const int lane = tid & 31;
    const int wid  = tid >> 5;
    const int wm   = wid & 3;       // 4 warps over M (64 rows each)
    const int wn   = wid >> 2;      // 2 warps over N (64 cols each)
    const int sub  = lane >> 3;
    const int n0 = blockIdx.x << 7;
    const int m0 = blockIdx.y << 8;
    const int z  = (mode == 1) ? (int)blockIdx.z : 3;

    const __half* __restrict__ Ah = (mode == 1) ? g_xh : g_yh;
    const __half* __restrict__ Al = (mode == 1) ? g_xl : g_yl;

    if (tid == 0) {
        asm volatile("mbarrier.init.shared.b64 [%0], %1;" :: "r"(HDR),     "r"(1u) : "memory");
        asm volatile("mbarrier.init.shared.b64 [%0], %1;" :: "r"(HDR + 8), "r"(1u) : "memory");
    }
    __syncthreads();

    float acc[4][8][4];
    #pragma unroll
    for (int mi = 0; mi < 4; ++mi)
        #pragma unroll
        for (int ng = 0; ng < 8; ++ng)
            #pragma unroll
            for (int j = 0; j < 4; ++j) acc[mi][ng][j] = 0.f;

    auto issue = [&](int ci, int st) {
        uint32_t mb = HDR + st * 8;
        uint32_t db = TIL + st * STAGE_B;
        asm volatile("mbarrier.arrive.expect_tx.shared.b64 _, [%0], %1;"
                     :: "r"(mb), "r"((uint32_t)STAGE_B) : "memory");
        bulk_cp(db,               Ah   + (((size_t)ci * M_TOTAL + m0) << 6), TILE_AH, mb);
        bulk_cp(db + TILE_AH,     Al   + (((size_t)ci * M_TOTAL + m0) << 6), TILE_AH, mb);
        bulk_cp(db + 2 * TILE_AH, g_wh + ((((size_t)z * NCH + ci) * E_ + n0) << 6), TILE_BH, mb);
        bulk_cp(db + 2 * TILE_AH + TILE_BH,
                                  g_wl + ((((size_t)z * NCH + ci) * E_ + n0) << 6), TILE_BH, mb);
    };

    if (tid == 0) issue(0, 0);

    for (int i = 0; i < NCH; ++i) {
        if (i + 1 < NCH && tid == 0) issue(i + 1, (i + 1) & 1);
        const int st = i & 1;
        mbar_wait(HDR + st * 8, (uint32_t)((i >> 1) & 1));
        const uint32_t baseA = TIL + st * STAGE_B;
        const uint32_t baseB = baseA + 2 * TILE_AH;

        #pragma unroll
        for (int ks = 0; ks < 4; ++ks) {
            uint32_t Af[2][4][4];
            {
                const int ar0 = wm * 64 + (lane & 7) + ((sub & 1) << 3);
                const int akc = ks * 2 + (sub >> 1);
                #pragma unroll
                for (int mi = 0; mi < 4; ++mi) {
                    int r = ar0 + mi * 16;
                    uint32_t off = (uint32_t)(r * 128 + ((akc ^ (r & 7)) << 4));
                    LDSM4(Af[0][mi], baseA + off);
                    LDSM4(Af[1][mi], baseA + TILE_AH + off);
                }
            }
            uint32_t Bf[2][4][4];
            {
                const int br0 = wn * 64 + (lane & 7) + ((sub >> 1) << 3);
                const int bkc = ks * 2 + (sub & 1);
                #pragma unroll
                for (int g = 0; g < 4; ++g) {
                    int r = br0 + g * 16;
                    uint32_t off = (uint32_t)(r * 128 + ((bkc ^ (r & 7)) << 4));
                    LDSM4(Bf[0][g], baseB + off);
                    LDSM4(Bf[1][g], baseB + TILE_BH + off);
                }
            }
            #pragma unroll
            for (int mi = 0; mi < 4; ++mi)
                #pragma unroll
                for (int ng = 0; ng < 8; ++ng) {
                    const int g = ng >> 1, o = (ng & 1) << 1;
                    MMA16816(acc[mi][ng], Af[0][mi], &Bf[0][g][o]);   // hh
                    MMA16816(acc[mi][ng], Af[0][mi], &Bf[1][g][o]);   // h*l
                    MMA16816(acc[mi][ng], Af[1][mi], &Bf[0][g][o]);   // l*h
                }
        }
        __syncthreads();
    }

    // ---- epilogue ----
    const int col2 = (lane & 3) << 1;
    const int h = (n0 >> 6) + wn;
    #pragma unroll
    for (int mi = 0; mi < 4; ++mi) {
        #pragma unroll
        for (int rr = 0; rr < 2; ++rr) {
            const int m = m0 + wm * 64 + mi * 16 + rr * 8 + (lane >> 2);
            if (mode == 0) {
                float* dp = Cout + (size_t)m * E_ + n0 + wn * 64;
                #pragma unroll
                for (int ng = 0; ng < 8; ++ng) {
                    float2 v = make_float2(acc[mi][ng][rr * 2], acc[mi][ng][rr * 2 + 1]);
                    *(float2*)(dp + ng * 8 + col2) = v;
                }
            } else {
                const int bb = m >> 11, ss = m & (S_ - 1);
                const int rsw = ss & 7;
                if (z == 2) {
                    size_t base = ((((size_t)(bb * H_ + h) * (S_ / 64) + (ss >> 6)) * 64
                                    + (ss & 63)) << 6);
                    #pragma unroll
                    for (int ng = 0; ng < 8; ++ng) {
                        int d = ng * 8 + col2;
                        uint32_t lo, hi = pack_hl(acc[mi][ng][rr*2], acc[mi][ng][rr*2+1], lo);
                        size_t idx = base + ((((d >> 3) ^ rsw) << 3) | (d & 7));
                        *(uint32_t*)&g_vf_h[idx] = hi;
                        *(uint32_t*)&g_vf_l[idx] = lo;
                    }
                } else {
                    float r1[4][2], r2[4][2];
                    #pragma unroll
                    for (int ng = 0; ng < 4; ++ng)
                        #pragma unroll
                        for (int jj = 0; jj < 2; ++jj) {
                            const int d = ng * 8 + col2 + jj;
                            float x1 = acc[mi][ng][rr * 2 + jj];
                            float x2 = acc[mi][ng + 4][rr * 2 + jj];
                            float c  = g_cos[(ss << 5) + d];
                            float sn = g_sin[(ss << 5) + d];
                            float v1 = x1 * c - x2 * sn;
                            float v2 = x2 * c + x1 * sn;
                            if (z == 0) { v1 *= 0.125f; v2 *= 0.125f; }
                            r1[ng][jj] = v1; r2[ng][jj] = v2;
                        }
                    size_t base;
                    __half *ph, *pl;
                    if (z == 0) {
                        base = ((((size_t)(bb * H_ + h) * (S_ / 128) + (ss >> 7)) * 128
                                 + (ss & 127)) << 6);
                        ph = g_qf_h; pl = g_qf_l;
                    } else {
                        base = ((((size_t)(bb * H_ + h) * (S_ / 64) + (ss >> 6)) * 64
                                 + (ss & 63)) << 6);
                        ph = g_kf_h; pl = g_kf_l;
                    }
                    #pragma unroll
                    for (int ng = 0; ng < 4; ++ng) {
                        int d = ng * 8 + col2;
                        uint32_t lo, hi = pack_hl(r1[ng][0], r1[ng][1], lo);
                        size_t idx = base + ((((d >> 3) ^ rsw) << 3) | (d & 7));
                        *(uint32_t*)&ph[idx] = hi;
                        *(uint32_t*)&pl[idx] = lo;
                        int d2 = d + 32;
                        uint32_t lo2, hi2 = pack_hl(r2[ng][0], r2[ng][1], lo2);
                        size_t idx2 = base + ((((d2 >> 3) ^ rsw) << 3) | (d2 & 7));
                        *(uint32_t*)&ph[idx2] = hi2;
                        *(uint32_t*)&pl[idx2] = lo2;
                    }
                }
            }
        }
    }
}

// ---------------- HMMA windowed flash attention ----------------
// grid (S/128, H, B), 256 threads (8 warps x 16 query rows).
#define Q_BYTES   16384
#define KV_TILE   8192
#define KV_STAGE  32768
#define SMEM_ATTN (1024 + 2*Q_BYTES + 2*KV_STAGE)

__global__ __launch_bounds__(256) void attn_kernel() {
    extern __shared__ char smraw[];
    const uint32_t raw = smem_u32(smraw);
    const uint32_t HDR  = (raw + 1023) & ~1023u;
    const uint32_t TILQ = HDR + 1024;
    const uint32_t KVB  = TILQ + 2 * Q_BYTES;

    const int tid  = threadIdx.x;
    const int lane = tid & 31;
    const int wid  = tid >> 5;
    const int sub  = lane >> 3;
    const int g    = lane >> 2;
    const int t2   = (lane & 3) << 1;
    const int qt = blockIdx.x;
    const int q0 = qt << 7;
    const int h  = blockIdx.y;
    const int b  = blockIdx.z;
    const int bh = b * H_ + h;
    const int wrow = wid * 16;

    if (tid == 0) {
        asm volatile("mbarrier.init.shared.b64 [%0], %1;" :: "r"(HDR),      "r"(1u) : "memory");
        asm volatile("mbarrier.init.shared.b64 [%0], %1;" :: "r"(HDR + 8),  "r"(1u) : "memory");
        asm volatile("mbarrier.init.shared.b64 [%0], %1;" :: "r"(HDR + 16), "r"(1u) : "memory");
    }
    __syncthreads();

    const int kt0 = (q0 >= WIN_) ? ((q0 - WIN_ + 1) >> 6) : 0;
    const int kt1 = (q0 + 127) >> 6;
    const int nt  = kt1 - kt0 + 1;

    auto issueKV = [&](int kt, int j) {
        int st = j & 1;
        uint32_t mb = HDR + 8 + st * 8;
        uint32_t db = KVB + st * KV_STAGE;
        asm volatile("mbarrier.arrive.expect_tx.shared.b64 _, [%0], %1;"
                     :: "r"(mb), "r"((uint32_t)KV_STAGE) : "memory");
        const size_t tb = ((size_t)bh * (S_ / 64) + kt) << 12;
        bulk_cp(db,               g_kf_h + tb, KV_TILE, mb);
        bulk_cp(db + KV_TILE,     g_kf_l + tb, KV_TILE, mb);
        bulk_cp(db + 2 * KV_TILE, g_vf_h + tb, KV_TILE, mb);
        bulk_cp(db + 3 * KV_TILE, g_vf_l + tb, KV_TILE, mb);
    };

    if (tid == 0) {
        asm volatile("mbarrier.arrive.expect_tx.shared.b64 _, [%0], %1;"
                     :: "r"(HDR), "r"((uint32_t)(2 * Q_BYTES)) : "memory");
        const size_t qb = ((size_t)bh * (S_ / 128) + qt) << 13;
        bulk_cp(TILQ,           g_qf_h + qb, Q_BYTES, HDR);
        bulk_cp(TILQ + Q_BYTES, g_qf_l + qb, Q_BYTES, HDR);
        issueKV(kt0, 0);
        if (nt > 1) issueKV(kt0 + 1, 1);
    }

    uint32_t Aqh[4][4], Aql[4][4];
    mbar_wait(HDR, 0u);
    {
        const int r = wrow + (lane & 7) + ((sub & 1) << 3);
        #pragma unroll
        for (int ks = 0; ks < 4; ++ks) {
            uint32_t off = (uint32_t)(r * 128 + (((ks * 2 + (sub >> 1)) ^ (r & 7)) << 4));
            LDSM4(Aqh[ks], TILQ + off);
            LDSM4(Aql[ks], TILQ + Q_BYTES + off);
        }
    }

    float oacc[8][4];
    #pragma unroll
    for (int dg = 0; dg < 8; ++dg)
        #pragma unroll
        for (int j = 0; j < 4; ++j) oacc[dg][j] = 0.f;
    float mrow[2] = {-1e30f, -1e30f};
    float lrow[2] = {0.f, 0.f};
    const int sq0 = q0 + wrow + g;

    for (int j = 0; j < nt; ++j) {
        const int jb = (kt0 + j) << 6;
        const int st = j & 1;
        mbar_wait(HDR + 8 + st * 8, (uint32_t)((j >> 1) & 1));
        const uint32_t kb_h = KVB + st * KV_STAGE;
        const uint32_t kb_l = kb_h + KV_TILE;
        const uint32_t vb_h = kb_h + 2 * KV_TILE;
        const uint32_t vb_l = kb_h + 3 * KV_TILE;

        float sacc[8][4];
        #pragma unroll
        for (int cg = 0; cg < 8; ++cg)
            #pragma unroll
            for (int jj = 0; jj < 4; ++jj) sacc[cg][jj] = 0.f;

        #pragma unroll
        for (int ks = 0; ks < 4; ++ks) {
            #pragma unroll
            for (int kg = 0; kg < 4; ++kg) {
                uint32_t Bh[4], Bl[4];
                const int r = kg * 16 + (lane & 7) + ((sub >> 1) << 3);
                uint32_t off = (uint32_t)(r * 128 + (((ks * 2 + (sub & 1)) ^ (r & 7)) << 4));
                LDSM4(Bh, kb_h + off);
                LDSM4(Bl, kb_l + off);
                MMA16816(sacc[kg*2],   Aqh[ks], &Bh[0]);
                MMA16816(sacc[kg*2],   Aqh[ks], &Bl[0]);
                MMA16816(sacc[kg*2],   Aql[ks], &Bh[0]);
                MMA16816(sacc[kg*2+1], Aqh[ks], &Bh[2]);
                MMA16816(sacc[kg*2+1], Aqh[ks], &Bl[2]);
                MMA16816(sacc[kg*2+1], Aql[ks], &Bh[2]);
            }
        }

        float mx[2] = {-1e30f, -1e30f};
        #pragma unroll
        for (int cg = 0; cg < 8; ++cg) {
            const int jp = jb + cg * 8 + t2;
            #pragma unroll
            for (int rh = 0; rh < 2; ++rh) {
                const int sq = sq0 + rh * 8;
                #pragma unroll
                for (int jj = 0; jj < 2; ++jj) {
                    float& s = sacc[cg][rh * 2 + jj];
                    const int jpos = jp + jj;
                    bool ok = (jpos <= sq) && (sq - jpos < WIN_);
                    if (!ok) s = -1e30f;
                    mx[rh] = fmaxf(mx[rh], s);
                }
            }
        }
        #pragma unroll
        for (int off = 1; off < 4; off <<= 1) {
            mx[0] = fmaxf(mx[0], __shfl_xor_sync(0xFFFFFFFFu, mx[0], off));
            mx[1] = fmaxf(mx[1], __shfl_xor_sync(0xFFFFFFFFu, mx[1], off));
        }
        float mn[2], al[2], safe[2];
        #pragma unroll
        for (int rh = 0; rh < 2; ++rh) {
            mn[rh]   = fmaxf(mrow[rh], mx[rh]);
            al[rh]   = __expf(mrow[rh] - mn[rh]);
            safe[rh] = (mn[rh] < -1e29f) ? 0.f : mn[rh];
            mrow[rh] = mn[rh];
            lrow[rh] *= al[rh];
        }
        #pragma unroll
        for (int cg = 0; cg < 8; ++cg)
            #pragma unroll
            for (int rh = 0; rh < 2; ++rh)
                #pragma unroll
                for (int jj = 0; jj < 2; ++jj) {
                    float p = __expf(sacc[cg][rh * 2 + jj] - safe[rh]);
                    sacc[cg][rh * 2 + jj] = p;
                    lrow[rh] += p;
                }
        #pragma unroll
        for (int dg = 0; dg < 8; ++dg) {
            oacc[dg][0] *= al[0]; oacc[dg][1] *= al[0];
            oacc[dg][2] *= al[1]; oacc[dg][3] *= al[1];
        }

        #pragma unroll
        for (int kc4 = 0; kc4 < 4; ++kc4) {
            uint32_t ph[4], pl[4];
            ph[0] = pack_hl(sacc[kc4*2][0],   sacc[kc4*2][1],   pl[0]);
            ph[1] = pack_hl(sacc[kc4*2][2],   sacc[kc4*2][3],   pl[1]);
            ph[2] = pack_hl(sacc[kc4*2+1][0], sacc[kc4*2+1][1], pl[2]);
            ph[3] = pack_hl(sacc[kc4*2+1][2], sacc[kc4*2+1][3], pl[3]);
            const int r = kc4 * 16 + (lane & 7) + ((sub & 1) << 3);
            #pragma unroll
            for (int dg4 = 0; dg4 < 4; ++dg4) {
                uint32_t Vh[4], Vl[4];
                uint32_t off = (uint32_t)(r * 128 + (((dg4 * 2 + (sub >> 1)) ^ (r & 7)) << 4));
                LDSM4T(Vh, vb_h + off);
                LDSM4T(Vl, vb_l + off);
                MMA16816(oacc[dg4*2],   ph, &Vh[0]);
                MMA16816(oacc[dg4*2],   ph, &Vl[0]);
                MMA16816(oacc[dg4*2],   pl, &Vh[0]);
                MMA16816(oacc[dg4*2+1], ph, &Vh[2]);
                MMA16816(oacc[dg4*2+1], ph, &Vl[2]);
                MMA16816(oacc[dg4*2+1], pl, &Vh[2]);
            }
        }

        __syncthreads();
        if (tid == 0 && j + 2 < nt) issueKV(kt0 + j + 2, j + 2);
    }

    #pragma unroll
    for (int off = 1; off < 4; off <<= 1) {
        lrow[0] += __shfl_xor_sync(0xFFFFFFFFu, lrow[0], off);
        lrow[1] += __shfl_xor_sync(0xFFFFFFFFu, lrow[1], off);
    }
    float inv[2] = {1.f / lrow[0], 1.f / lrow[1]};
    #pragma unroll
    for (int rh = 0; rh < 2; ++rh) {
        const int m = b * S_ + sq0 + rh * 8;
        const size_t base = ((size_t)h * M_TOTAL + m) << 6;
        const int rsw = m & 7;
        #pragma unroll
        for (int dg = 0; dg < 8; ++dg) {
            int d = dg * 8 + t2;
            float v0 = oacc[dg][rh * 2]     * inv[rh];
            float v1 = oacc[dg][rh * 2 + 1] * inv[rh];
            uint32_t lo, hi = pack_hl(v0, v1, lo);
            size_t idx = base + (((dg ^ rsw) << 3) | (d & 7));
            *(uint32_t*)&g_yh[idx] = hi;
            *(uint32_t*)&g_yl[idx] = lo;
        }
    }
}

// ---------------- launch ----------------
extern "C" void kernel_launch(void* const* d_in, const int* in_sizes, int n_in,
                              void* d_out, int out_size)
{
    const float* x  = (const float*)d_in[0];
    const float* Wq = (const float*)d_in[1];
    const float* Wk = (const float*)d_in[2];
    const float* Wv = (const float*)d_in[3];
    const float* Wo = (const float*)d_in[4];
    float* out = (float*)d_out;

    cudaFuncSetAttribute(gemm_f16_kernel,
                         cudaFuncAttributeMaxDynamicSharedMemorySize, SMEM_BYTES);
    cudaFuncSetAttribute(attn_kernel,
                         cudaFuncAttributeMaxDynamicSharedMemorySize, SMEM_ATTN);

    rope_table_kernel<<<(S_ * 32 + 255) / 256, 256>>>();
    conv_x_kernel<<<(M_TOTAL * E_) / 256, 256>>>(x);
    conv_w_kernel<<<(4 * E_ * E_) / 256, 256>>>(Wq, Wk, Wv, Wo);

    dim3 g1(E_ / 128, M_TOTAL / 256, 3);   // (8, 16, 3)
    gemm_f16_kernel<<<g1, 256, SMEM_BYTES>>>(1, nullptr);

    dim3 ga(S_ / 128, H_, B_);
    attn_kernel<<<ga, 256, SMEM_ATTN>>>();

    dim3 g2(E_ / 128, M_TOTAL / 256, 1);   // (8, 16)
    gemm_f16_kernel<<<g2, 256, SMEM_BYTES>>>(0, out);
}

// round 6
// speedup vs baseline: 4.4742x; 1.2392x over previous
#include <cuda_runtime.h>
#include <cuda_fp16.h>
#include <math.h>
#include <stdint.h>

#define B_ 2
#define S_ 2048
#define E_ 1024
#define H_ 16
#define D_ 64
#define WIN_ 256
#define M_TOTAL (B_*S_)          // 4096
#define NCH 16                    // K chunks of 64

// ---------------- scratch (device globals, allocation-free) ----------------
// GEMM operands: [kchunk 16][row 4096][64], 16B-chunk swizzled by (row&7)
__device__ __align__(1024) __half g_xh[NCH*M_TOTAL*64];
__device__ __align__(1024) __half g_xl[NCH*M_TOTAL*64];
__device__ __align__(1024) __half g_wh[4*NCH*E_*64];   // hi only (2-pass GEMM)
__device__ __align__(1024) __half g_yh[NCH*M_TOTAL*64];
__device__ __align__(1024) __half g_yl[NCH*M_TOTAL*64];
// attention operands (fp16 hi/lo, swizzled tiles):
// Q: [bh 32][qtile 16][128][64]   K/V: [bh 32][ktile 32][64][64]
__device__ __align__(1024) __half g_qf_h[B_*H_*S_*64];
__device__ __align__(1024) __half g_qf_l[B_*H_*S_*64];
__device__ __align__(1024) __half g_kf_h[B_*H_*S_*64];
__device__ __align__(1024) __half g_kf_l[B_*H_*S_*64];
__device__ __align__(1024) __half g_vf_h[B_*H_*S_*64];
__device__ __align__(1024) __half g_vf_l[B_*H_*S_*64];
__device__ float g_cos[S_*32];
__device__ float g_sin[S_*32];

// ---------------- PTX helpers ----------------
__device__ __forceinline__ uint32_t smem_u32(const void* p) {
    uint32_t a;
    asm("{ .reg .u64 t; cvta.to.shared.u64 t, %1; cvt.u32.u64 %0, t; }"
        : "=r"(a) : "l"(p));
    return a;
}

__device__ __forceinline__ void mbar_wait(uint32_t mbar, uint32_t parity) {
    asm volatile(
        "{\n\t.reg .pred P;\n\t"
        "WL%=:\n\t"
        "mbarrier.try_wait.parity.acquire.cta.shared::cta.b64 P, [%0], %1, 0x989680;\n\t"
        "@P bra WD%=;\n\t"
        "bra WL%=;\n\t"
        "WD%=:\n\t}"
        :: "r"(mbar), "r"(parity) : "memory");
}

__device__ __forceinline__ void bulk_cp(uint32_t dst, const void* src, uint32_t bytes,
                                        uint32_t mbar) {
    asm volatile(
        "cp.async.bulk.shared::cluster.global.mbarrier::complete_tx::bytes [%0], [%1], %2, [%3];"
        :: "r"(dst), "l"(src), "r"(bytes), "r"(mbar) : "memory");
}

#define LDSM4(r, a) \
    asm volatile("ldmatrix.sync.aligned.m8n8.x4.shared.b16 {%0,%1,%2,%3}, [%4];" \
        : "=r"((r)[0]), "=r"((r)[1]), "=r"((r)[2]), "=r"((r)[3]) : "r"(a))

#define LDSM4T(r, a) \
    asm volatile("ldmatrix.sync.aligned.m8n8.x4.trans.shared.b16 {%0,%1,%2,%3}, [%4];" \
        : "=r"((r)[0]), "=r"((r)[1]), "=r"((r)[2]), "=r"((r)[3]) : "r"(a))

#define MMA16816(c, a, b) \
    asm volatile("mma.sync.aligned.m16n8k16.row.col.f32.f16.f16.f32 " \
        "{%0,%1,%2,%3}, {%4,%5,%6,%7}, {%8,%9}, {%0,%1,%2,%3};" \
        : "+f"((c)[0]), "+f"((c)[1]), "+f"((c)[2]), "+f"((c)[3]) \
        : "r"((a)[0]), "r"((a)[1]), "r"((a)[2]), "r"((a)[3]), \
          "r"((b)[0]), "r"((b)[1]))

// fp32 pair -> fp16 hi/lo half2 (bit-packed)
__device__ __forceinline__ uint32_t pack_hl(float a, float b, uint32_t& lo) {
    __half2 h = __floats2half2_rn(a, b);
    float2 bk = __half22float2(h);
    __half2 l = __floats2half2_rn(a - bk.x, b - bk.y);
    lo = *(uint32_t*)&l;
    return *(uint32_t*)&h;
}

// ---------------- RoPE table ----------------
__global__ void rope_table_kernel() {
    int i = blockIdx.x * blockDim.x + threadIdx.x;
    if (i >= S_ * 32) return;
    int s = i >> 5, j = i & 31;
    double invf = pow(10000.0, -(double)j / 32.0);
    double ang  = (double)s * invf;
    g_cos[i] = (float)cos(ang);
    g_sin[i] = (float)sin(ang);
}

// ---------------- fp32 -> pre-tiled pre-swizzled fp16 hi/lo ----------------
__global__ void conv_x_kernel(const float* __restrict__ x) {
    int i = blockIdx.x * blockDim.x + threadIdx.x;
    if (i >= M_TOTAL * E_) return;
    int m = i >> 10, k = i & 1023;
    float v = x[i];
    __half h = __float2half_rn(v);
    __half l = __float2half_rn(v - __half2float(h));
    int k63 = k & 63;
    size_t idx = (((size_t)(k >> 6) * M_TOTAL + m) << 6)
               + ((((k63 >> 3) ^ (m & 7)) << 3) | (k63 & 7));
    g_xh[idx] = h; g_xl[idx] = l;
}

__global__ void conv_w_kernel(const float* __restrict__ Wq, const float* __restrict__ Wk,
                              const float* __restrict__ Wv, const float* __restrict__ Wo) {
    int i = blockIdx.x * blockDim.x + threadIdx.x;
    if (i >= 4 * E_ * E_) return;
    int z = i >> 20;
    int j = i & (E_ * E_ - 1);
    int n = j >> 10, k = j & 1023;
    const float* p = (z == 0) ? Wq : (z == 1) ? Wk : (z == 2) ? Wv : Wo;
    float v = p[j];
    int c = (k >> 3) & 7, w = k & 7;
    size_t idx = ((((size_t)z * NCH + (k >> 6)) * E_ + n) << 6)
               + (((c ^ (n & 7)) << 3) | w);
    g_wh[idx] = __float2half_rn(v);
}

// ---------------- HMMA fp16 2-pass GEMM: C = A @ W^T ----------------
// CTA tile 256x128, 8 warps (4M x 2N), warp tile 64x64, K chunks of 64.
// D = Ah*Wh + Al*Wh  (W-lo term dropped; error ~1.6e-4 relative)
#define TILE_AH 32768                       // 256 rows x 64 halves x 2B
#define TILE_BH 16384                       // 128 rows x 64 halves x 2B
#define STAGE_B (2*TILE_AH + TILE_BH)       // 80 KB
#define SMEM_BYTES (1024 + 2*STAGE_B)       // ~161 KB

__global__ __launch_bounds__(256) void gemm_f16_kernel(int mode, float* __restrict__ Cout)
{
    extern __shared__ char smraw[];
    const uint32_t raw = smem_u32(smraw);
    const uint32_t HDR = (raw + 1023) & ~1023u;
    const uint32_t TIL = HDR + 1024;

    const int tid  = threadIdx.x;
    const int lane = tid & 31;
    const int wid  = tid >> 5;
    const int wm   = wid & 3;       // 4 warps over M (64 rows each)
    const int wn   = wid >> 2;      // 2 warps over N (64 cols each)
    const int sub  = lane >> 3;
    const int n0 = blockIdx.x << 7;
    const int m0 = blockIdx.y << 8;
    const int z  = (mode == 1) ? (int)blockIdx.z : 3;

    const __half* __restrict__ Ah = (mode == 1) ? g_xh : g_yh;
    const __half* __restrict__ Al = (mode == 1) ? g_xl : g_yl;

    if (tid == 0) {
        asm volatile("mbarrier.init.shared.b64 [%0], %1;" :: "r"(HDR),     "r"(1u) : "memory");
        asm volatile("mbarrier.init.shared.b64 [%0], %1;" :: "r"(HDR + 8), "r"(1u) : "memory");
    }
    __syncthreads();

    float acc[4][8][4];
    #pragma unroll
    for (int mi = 0; mi < 4; ++mi)
        #pragma unroll
        for (int ng = 0; ng < 8; ++ng)
            #pragma unroll
            for (int j = 0; j < 4; ++j) acc[mi][ng][j] = 0.f;

    auto issue = [&](int ci, int st) {
        uint32_t mb = HDR + st * 8;
        uint32_t db = TIL + st * STAGE_B;
        asm volatile("mbarrier.arrive.expect_tx.shared.b64 _, [%0], %1;"
                     :: "r"(mb), "r"((uint32_t)STAGE_B) : "memory");
        bulk_cp(db,               Ah   + (((size_t)ci * M_TOTAL + m0) << 6), TILE_AH, mb);
        bulk_cp(db + TILE_AH,     Al   + (((size_t)ci * M_TOTAL + m0) << 6), TILE_AH, mb);
        bulk_cp(db + 2 * TILE_AH, g_wh + ((((size_t)z * NCH + ci) * E_ + n0) << 6), TILE_BH, mb);
    };

    if (tid == 0) issue(0, 0);

    for (int i = 0; i < NCH; ++i) {
        if (i + 1 < NCH && tid == 0) issue(i + 1, (i + 1) & 1);
        const int st = i & 1;
        mbar_wait(HDR + st * 8, (uint32_t)((i >> 1) & 1));
        const uint32_t baseA = TIL + st * STAGE_B;
        const uint32_t baseB = baseA + 2 * TILE_AH;

        #pragma unroll
        for (int ks = 0; ks < 4; ++ks) {
            uint32_t Af[2][4][4];
            {
                const int ar0 = wm * 64 + (lane & 7) + ((sub & 1) << 3);
                const int akc = ks * 2 + (sub >> 1);
                #pragma unroll
                for (int mi = 0; mi < 4; ++mi) {
                    int r = ar0 + mi * 16;
                    uint32_t off = (uint32_t)(r * 128 + ((akc ^ (r & 7)) << 4));
                    LDSM4(Af[0][mi], baseA + off);
                    LDSM4(Af[1][mi], baseA + TILE_AH + off);
                }
            }
            uint32_t Bf[4][4];
            {
                const int br0 = wn * 64 + (lane & 7) + ((sub >> 1) << 3);
                const int bkc = ks * 2 + (sub & 1);
                #pragma unroll
                for (int g = 0; g < 4; ++g) {
                    int r = br0 + g * 16;
                    uint32_t off = (uint32_t)(r * 128 + ((bkc ^ (r & 7)) << 4));
                    LDSM4(Bf[g], baseB + off);
                }
            }
            #pragma unroll
            for (int mi = 0; mi < 4; ++mi)
                #pragma unroll
                for (int ng = 0; ng < 8; ++ng) {
                    const int g = ng >> 1, o = (ng & 1) << 1;
                    MMA16816(acc[mi][ng], Af[0][mi], &Bf[g][o]);   // hh
                    MMA16816(acc[mi][ng], Af[1][mi], &Bf[g][o]);   // lh
                }
        }
        __syncthreads();
    }

    // ---- epilogue ----
    const int col2 = (lane & 3) << 1;
    const int h = (n0 >> 6) + wn;
    #pragma unroll
    for (int mi = 0; mi < 4; ++mi) {
        #pragma unroll
        for (int rr = 0; rr < 2; ++rr) {
            const int m = m0 + wm * 64 + mi * 16 + rr * 8 + (lane >> 2);
            if (mode == 0) {
                float* dp = Cout + (size_t)m * E_ + n0 + wn * 64;
                #pragma unroll
                for (int ng = 0; ng < 8; ++ng) {
                    float2 v = make_float2(acc[mi][ng][rr * 2], acc[mi][ng][rr * 2 + 1]);
                    *(float2*)(dp + ng * 8 + col2) = v;
                }
            } else {
                const int bb = m >> 11, ss = m & (S_ - 1);
                const int rsw = ss & 7;
                if (z == 2) {
                    size_t base = ((((size_t)(bb * H_ + h) * (S_ / 64) + (ss >> 6)) * 64
                                    + (ss & 63)) << 6);
                    #pragma unroll
                    for (int ng = 0; ng < 8; ++ng) {
                        int d = ng * 8 + col2;
                        uint32_t lo, hi = pack_hl(acc[mi][ng][rr*2], acc[mi][ng][rr*2+1], lo);
                        size_t idx = base + ((((d >> 3) ^ rsw) << 3) | (d & 7));
                        *(uint32_t*)&g_vf_h[idx] = hi;
                        *(uint32_t*)&g_vf_l[idx] = lo;
                    }
                } else {
                    float r1[4][2], r2[4][2];
                    #pragma unroll
                    for (int ng = 0; ng < 4; ++ng)
                        #pragma unroll
                        for (int jj = 0; jj < 2; ++jj) {
                            const int d = ng * 8 + col2 + jj;
                            float x1 = acc[mi][ng][rr * 2 + jj];
                            float x2 = acc[mi][ng + 4][rr * 2 + jj];
                            float c  = g_cos[(ss << 5) + d];
                            float sn = g_sin[(ss << 5) + d];
                            float v1 = x1 * c - x2 * sn;
                            float v2 = x2 * c + x1 * sn;
                            if (z == 0) { v1 *= 0.125f; v2 *= 0.125f; }
                            r1[ng][jj] = v1; r2[ng][jj] = v2;
                        }
                    size_t base;
                    __half *ph, *pl;
                    if (z == 0) {
                        base = ((((size_t)(bb * H_ + h) * (S_ / 128) + (ss >> 7)) * 128
                                 + (ss & 127)) << 6);
                        ph = g_qf_h; pl = g_qf_l;
                    } else {
                        base = ((((size_t)(bb * H_ + h) * (S_ / 64) + (ss >> 6)) * 64
                                 + (ss & 63)) << 6);
                        ph = g_kf_h; pl = g_kf_l;
                    }
                    #pragma unroll
                    for (int ng = 0; ng < 4; ++ng) {
                        int d = ng * 8 + col2;
                        uint32_t lo, hi = pack_hl(r1[ng][0], r1[ng][1], lo);
                        size_t idx = base + ((((d >> 3) ^ rsw) << 3) | (d & 7));
                        *(uint32_t*)&ph[idx] = hi;
                        *(uint32_t*)&pl[idx] = lo;
                        int d2 = d + 32;
                        uint32_t lo2, hi2 = pack_hl(r2[ng][0], r2[ng][1], lo2);
                        size_t idx2 = base + ((((d2 >> 3) ^ rsw) << 3) | (d2 & 7));
                        *(uint32_t*)&ph[idx2] = hi2;
                        *(uint32_t*)&pl[idx2] = lo2;
                    }
                }
            }
        }
    }
}

// ---------------- HMMA windowed flash attention (3-pass split) ----------------
// grid (S/128, H, B), 256 threads (8 warps x 16 query rows).
#define Q_BYTES   16384
#define KV_TILE   8192
#define KV_STAGE  32768
#define SMEM_ATTN (1024 + 2*Q_BYTES + 2*KV_STAGE)

__global__ __launch_bounds__(256) void attn_kernel() {
    extern __shared__ char smraw[];
    const uint32_t raw = smem_u32(smraw);
    const uint32_t HDR  = (raw + 1023) & ~1023u;
    const uint32_t TILQ = HDR + 1024;
    const uint32_t KVB  = TILQ + 2 * Q_BYTES;

    const int tid  = threadIdx.x;
    const int lane = tid & 31;
    const int wid  = tid >> 5;
    const int sub  = lane >> 3;
    const int g    = lane >> 2;
    const int t2   = (lane & 3) << 1;
    const int qt = blockIdx.x;
    const int q0 = qt << 7;
    const int h  = blockIdx.y;
    const int b  = blockIdx.z;
    const int bh = b * H_ + h;
    const int wrow = wid * 16;

    if (tid == 0) {
        asm volatile("mbarrier.init.shared.b64 [%0], %1;" :: "r"(HDR),      "r"(1u) : "memory");
        asm volatile("mbarrier.init.shared.b64 [%0], %1;" :: "r"(HDR + 8),  "r"(1u) : "memory");
        asm volatile("mbarrier.init.shared.b64 [%0], %1;" :: "r"(HDR + 16), "r"(1u) : "memory");
    }
    __syncthreads();

    const int kt0 = (q0 >= WIN_) ? ((q0 - WIN_ + 1) >> 6) : 0;
    const int kt1 = (q0 + 127) >> 6;
    const int nt  = kt1 - kt0 + 1;

    auto issueKV = [&](int kt, int j) {
        int st = j & 1;
        uint32_t mb = HDR + 8 + st * 8;
        uint32_t db = KVB + st * KV_STAGE;
        asm volatile("mbarrier.arrive.expect_tx.shared.b64 _, [%0], %1;"
                     :: "r"(mb), "r"((uint32_t)KV_STAGE) : "memory");
        const size_t tb = ((size_t)bh * (S_ / 64) + kt) << 12;
        bulk_cp(db,               g_kf_h + tb, KV_TILE, mb);
        bulk_cp(db + KV_TILE,     g_kf_l + tb, KV_TILE, mb);
        bulk_cp(db + 2 * KV_TILE, g_vf_h + tb, KV_TILE, mb);
        bulk_cp(db + 3 * KV_TILE, g_vf_l + tb, KV_TILE, mb);
    };

    if (tid == 0) {
        asm volatile("mbarrier.arrive.expect_tx.shared.b64 _, [%0], %1;"
                     :: "r"(HDR), "r"((uint32_t)(2 * Q_BYTES)) : "memory");
        const size_t qb = ((size_t)bh * (S_ / 128) + qt) << 13;
        bulk_cp(TILQ,           g_qf_h + qb, Q_BYTES, HDR);
        bulk_cp(TILQ + Q_BYTES, g_qf_l + qb, Q_BYTES, HDR);
        issueKV(kt0, 0);
        if (nt > 1) issueKV(kt0 + 1, 1);
    }

    uint32_t Aqh[4][4], Aql[4][4];
    mbar_wait(HDR, 0u);
    {
        const int r = wrow + (lane & 7) + ((sub & 1) << 3);
        #pragma unroll
        for (int ks = 0; ks < 4; ++ks) {
            uint32_t off = (uint32_t)(r * 128 + (((ks * 2 + (sub >> 1)) ^ (r & 7)) << 4));
            LDSM4(Aqh[ks], TILQ + off);
            LDSM4(Aql[ks], TILQ + Q_BYTES + off);
        }
    }

    float oacc[8][4];
    #pragma unroll
    for (int dg = 0; dg < 8; ++dg)
        #pragma unroll
        for (int j = 0; j < 4; ++j) oacc[dg][j] = 0.f;
    float mrow[2] = {-1e30f, -1e30f};
    float lrow[2] = {0.f, 0.f};
    const int sq0 = q0 + wrow + g;

    for (int j = 0; j < nt; ++j) {
        const int jb = (kt0 + j) << 6;
        const int st = j & 1;
        mbar_wait(HDR + 8 + st * 8, (uint32_t)((j >> 1) & 1));
        const uint32_t kb_h = KVB + st * KV_STAGE;
        const uint32_t kb_l = kb_h + KV_TILE;
        const uint32_t vb_h = kb_h + 2 * KV_TILE;
        const uint32_t vb_l = kb_h + 3 * KV_TILE;

        float sacc[8][4];
        #pragma unroll
        for (int cg = 0; cg < 8; ++cg)
            #pragma unroll
            for (int jj = 0; jj < 4; ++jj) sacc[cg][jj] = 0.f;

        #pragma unroll
        for (int ks = 0; ks < 4; ++ks) {
            #pragma unroll
            for (int kg = 0; kg < 4; ++kg) {
                uint32_t Bh[4], Bl[4];
                const int r = kg * 16 + (lane & 7) + ((sub >> 1) << 3);
                uint32_t off = (uint32_t)(r * 128 + (((ks * 2 + (sub & 1)) ^ (r & 7)) << 4));
                LDSM4(Bh, kb_h + off);
                LDSM4(Bl, kb_l + off);
                MMA16816(sacc[kg*2],   Aqh[ks], &Bh[0]);
                MMA16816(sacc[kg*2],   Aqh[ks], &Bl[0]);
                MMA16816(sacc[kg*2],   Aql[ks], &Bh[0]);
                MMA16816(sacc[kg*2+1], Aqh[ks], &Bh[2]);
                MMA16816(sacc[kg*2+1], Aqh[ks], &Bl[2]);
                MMA16816(sacc[kg*2+1], Aql[ks], &Bh[2]);
            }
        }

        float mx[2] = {-1e30f, -1e30f};
        #pragma unroll
        for (int cg = 0; cg < 8; ++cg) {
            const int jp = jb + cg * 8 + t2;
            #pragma unroll
            for (int rh = 0; rh < 2; ++rh) {
                const int sq = sq0 + rh * 8;
                #pragma unroll
                for (int jj = 0; jj < 2; ++jj) {
                    float& s = sacc[cg][rh * 2 + jj];
                    const int jpos = jp + jj;
                    bool ok = (jpos <= sq) && (sq - jpos < WIN_);
                    if (!ok) s = -1e30f;
                    mx[rh] = fmaxf(mx[rh], s);
                }
            }
        }
        #pragma unroll
        for (int off = 1; off < 4; off <<= 1) {
            mx[0] = fmaxf(mx[0], __shfl_xor_sync(0xFFFFFFFFu, mx[0], off));
            mx[1] = fmaxf(mx[1], __shfl_xor_sync(0xFFFFFFFFu, mx[1], off));
        }
        float mn[2], al[2], safe[2];
        #pragma unroll
        for (int rh = 0; rh < 2; ++rh) {
            mn[rh]   = fmaxf(mrow[rh], mx[rh]);
            al[rh]   = __expf(mrow[rh] - mn[rh]);
            safe[rh] = (mn[rh] < -1e29f) ? 0.f : mn[rh];
            mrow[rh] = mn[rh];
            lrow[rh] *= al[rh];
        }
        #pragma unroll
        for (int cg = 0; cg < 8; ++cg)
            #pragma unroll
            for (int rh = 0; rh < 2; ++rh)
                #pragma unroll
                for (int jj = 0; jj < 2; ++jj) {
                    float p = __expf(sacc[cg][rh * 2 + jj] - safe[rh]);
                    sacc[cg][rh * 2 + jj] = p;
                    lrow[rh] += p;
                }
        #pragma unroll
        for (int dg = 0; dg < 8; ++dg) {
            oacc[dg][0] *= al[0]; oacc[dg][1] *= al[0];
            oacc[dg][2] *= al[1]; oacc[dg][3] *= al[1];
        }

        #pragma unroll
        for (int kc4 = 0; kc4 < 4; ++kc4) {
            uint32_t ph[4], pl[4];
            ph[0] = pack_hl(sacc[kc4*2][0],   sacc[kc4*2][1],   pl[0]);
            ph[1] = pack_hl(sacc[kc4*2][2],   sacc[kc4*2][3],   pl[1]);
            ph[2] = pack_hl(sacc[kc4*2+1][0], sacc[kc4*2+1][1], pl[2]);
            ph[3] = pack_hl(sacc[kc4*2+1][2], sacc[kc4*2+1][3], pl[3]);
            const int r = kc4 * 16 + (lane & 7) + ((sub & 1) << 3);
            #pragma unroll
            for (int dg4 = 0; dg4 < 4; ++dg4) {
                uint32_t Vh[4], Vl[4];
                uint32_t off = (uint32_t)(r * 128 + (((dg4 * 2 + (sub >> 1)) ^ (r & 7)) << 4));
                LDSM4T(Vh, vb_h + off);
                LDSM4T(Vl, vb_l + off);
                MMA16816(oacc[dg4*2],   ph, &Vh[0]);
                MMA16816(oacc[dg4*2],   ph, &Vl[0]);
                MMA16816(oacc[dg4*2],   pl, &Vh[0]);
                MMA16816(oacc[dg4*2+1], ph, &Vh[2]);
                MMA16816(oacc[dg4*2+1], ph, &Vl[2]);
                MMA16816(oacc[dg4*2+1], pl, &Vh[2]);
            }
        }

        __syncthreads();
        if (tid == 0 && j + 2 < nt) issueKV(kt0 + j + 2, j + 2);
    }

    #pragma unroll
    for (int off = 1; off < 4; off <<= 1) {
        lrow[0] += __shfl_xor_sync(0xFFFFFFFFu, lrow[0], off);
        lrow[1] += __shfl_xor_sync(0xFFFFFFFFu, lrow[1], off);
    }
    float inv[2] = {1.f / lrow[0], 1.f / lrow[1]};
    #pragma unroll
    for (int rh = 0; rh < 2; ++rh) {
        const int m = b * S_ + sq0 + rh * 8;
        const size_t base = ((size_t)h * M_TOTAL + m) << 6;
        const int rsw = m & 7;
        #pragma unroll
        for (int dg = 0; dg < 8; ++dg) {
            int d = dg * 8 + t2;
            float v0 = oacc[dg][rh * 2]     * inv[rh];
            float v1 = oacc[dg][rh * 2 + 1] * inv[rh];
            uint32_t lo, hi = pack_hl(v0, v1, lo);
            size_t idx = base + (((dg ^ rsw) << 3) | (d & 7));
            *(uint32_t*)&g_yh[idx] = hi;
            *(uint32_t*)&g_yl[idx] = lo;
        }
    }
}

// ---------------- launch ----------------
extern "C" void kernel_launch(void* const* d_in, const int* in_sizes, int n_in,
                              void* d_out, int out_size)
{
    const float* x  = (const float*)d_in[0];
    const float* Wq = (const float*)d_in[1];
    const float* Wk = (const float*)d_in[2];
    const float* Wv = (const float*)d_in[3];
    const float* Wo = (const float*)d_in[4];
    float* out = (float*)d_out;

    cudaFuncSetAttribute(gemm_f16_kernel,
                         cudaFuncAttributeMaxDynamicSharedMemorySize, SMEM_BYTES);
    cudaFuncSetAttribute(attn_kernel,
                         cudaFuncAttributeMaxDynamicSharedMemorySize, SMEM_ATTN);

    rope_table_kernel<<<(S_ * 32 + 255) / 256, 256>>>();
    conv_x_kernel<<<(M_TOTAL * E_) / 256, 256>>>(x);
    conv_w_kernel<<<(4 * E_ * E_) / 256, 256>>>(Wq, Wk, Wv, Wo);

    dim3 g1(E_ / 128, M_TOTAL / 256, 3);   // (8, 16, 3)
    gemm_f16_kernel<<<g1, 256, SMEM_BYTES>>>(1, nullptr);

    dim3 ga(S_ / 128, H_, B_);
    attn_kernel<<<ga, 256, SMEM_ATTN>>>();

    dim3 g2(E_ / 128, M_TOTAL / 256, 1);   // (8, 16)
    gemm_f16_kernel<<<g2, 256, SMEM_BYTES>>>(0, out);
}

// round 7
// speedup vs baseline: 4.6818x; 1.0464x over previous
#include <cuda_runtime.h>
#include <cuda_fp16.h>
#include <math.h>
#include <stdint.h>

#define B_ 2
#define S_ 2048
#define E_ 1024
#define H_ 16
#define D_ 64
#define WIN_ 256
#define M_TOTAL (B_*S_)          // 4096
#define NCH 16                    // K chunks of 64

// ---------------- scratch (device globals, allocation-free) ----------------
__device__ __align__(1024) __half g_xh[NCH*M_TOTAL*64];
__device__ __align__(1024) __half g_xl[NCH*M_TOTAL*64];
__device__ __align__(1024) __half g_wh[4*NCH*E_*64];   // hi only (2-pass GEMM)
__device__ __align__(1024) __half g_yh[NCH*M_TOTAL*64];
__device__ __align__(1024) __half g_yl[NCH*M_TOTAL*64];
__device__ __align__(1024) __half g_qf_h[B_*H_*S_*64];
__device__ __align__(1024) __half g_qf_l[B_*H_*S_*64];
__device__ __align__(1024) __half g_kf_h[B_*H_*S_*64];
__device__ __align__(1024) __half g_kf_l[B_*H_*S_*64];
__device__ __align__(1024) __half g_vf_h[B_*H_*S_*64];
__device__ __align__(1024) __half g_vf_l[B_*H_*S_*64];
__device__ float g_cos[S_*32];
__device__ float g_sin[S_*32];

// ---------------- PTX helpers ----------------
__device__ __forceinline__ uint32_t smem_u32(const void* p) {
    uint32_t a;
    asm("{ .reg .u64 t; cvta.to.shared.u64 t, %1; cvt.u32.u64 %0, t; }"
        : "=r"(a) : "l"(p));
    return a;
}

__device__ __forceinline__ uint32_t elect1() {
    uint32_t p;
    asm volatile("{\n\t.reg .pred p;\n\telect.sync _|p, 0xFFFFFFFF;\n\t"
                 "selp.b32 %0, 1, 0, p;\n\t}" : "=r"(p));
    return p;
}

__device__ __forceinline__ void mbar_wait(uint32_t mbar, uint32_t parity) {
    asm volatile(
        "{\n\t.reg .pred P;\n\t"
        "WL%=:\n\t"
        "mbarrier.try_wait.parity.acquire.cta.shared::cta.b64 P, [%0], %1, 0x989680;\n\t"
        "@P bra WD%=;\n\t"
        "bra WL%=;\n\t"
        "WD%=:\n\t}"
        :: "r"(mbar), "r"(parity) : "memory");
}

__device__ __forceinline__ void mbar_arrive(uint32_t mbar) {
    asm volatile("mbarrier.arrive.shared.b64 _, [%0];" :: "r"(mbar) : "memory");
}

__device__ __forceinline__ void bulk_cp(uint32_t dst, const void* src, uint32_t bytes,
                                        uint32_t mbar) {
    asm volatile(
        "cp.async.bulk.shared::cluster.global.mbarrier::complete_tx::bytes [%0], [%1], %2, [%3];"
        :: "r"(dst), "l"(src), "r"(bytes), "r"(mbar) : "memory");
}

#define LDSM4(r, a) \
    asm volatile("ldmatrix.sync.aligned.m8n8.x4.shared.b16 {%0,%1,%2,%3}, [%4];" \
        : "=r"((r)[0]), "=r"((r)[1]), "=r"((r)[2]), "=r"((r)[3]) : "r"(a))

#define LDSM4T(r, a) \
    asm volatile("ldmatrix.sync.aligned.m8n8.x4.trans.shared.b16 {%0,%1,%2,%3}, [%4];" \
        : "=r"((r)[0]), "=r"((r)[1]), "=r"((r)[2]), "=r"((r)[3]) : "r"(a))

#define MMA16816(c, a, b) \
    asm volatile("mma.sync.aligned.m16n8k16.row.col.f32.f16.f16.f32 " \
        "{%0,%1,%2,%3}, {%4,%5,%6,%7}, {%8,%9}, {%0,%1,%2,%3};" \
        : "+f"((c)[0]), "+f"((c)[1]), "+f"((c)[2]), "+f"((c)[3]) \
        : "r"((a)[0]), "r"((a)[1]), "r"((a)[2]), "r"((a)[3]), \
          "r"((b)[0]), "r"((b)[1]))

__device__ __forceinline__ uint32_t pack_hl(float a, float b, uint32_t& lo) {
    __half2 h = __floats2half2_rn(a, b);
    float2 bk = __half22float2(h);
    __half2 l = __floats2half2_rn(a - bk.x, b - bk.y);
    lo = *(uint32_t*)&l;
    return *(uint32_t*)&h;
}

// ---------------- RoPE table ----------------
__global__ void rope_table_kernel() {
    int i = blockIdx.x * blockDim.x + threadIdx.x;
    if (i >= S_ * 32) return;
    int s = i >> 5, j = i & 31;
    double invf = pow(10000.0, -(double)j / 32.0);
    double ang  = (double)s * invf;
    g_cos[i] = (float)cos(ang);
    g_sin[i] = (float)sin(ang);
}

// ---------------- fp32 -> pre-tiled pre-swizzled fp16 hi/lo ----------------
__global__ void conv_x_kernel(const float* __restrict__ x) {
    int i = blockIdx.x * blockDim.x + threadIdx.x;
    if (i >= M_TOTAL * E_) return;
    int m = i >> 10, k = i & 1023;
    float v = x[i];
    __half h = __float2half_rn(v);
    __half l = __float2half_rn(v - __half2float(h));
    int k63 = k & 63;
    size_t idx = (((size_t)(k >> 6) * M_TOTAL + m) << 6)
               + ((((k63 >> 3) ^ (m & 7)) << 3) | (k63 & 7));
    g_xh[idx] = h; g_xl[idx] = l;
}

__global__ void conv_w_kernel(const float* __restrict__ Wq, const float* __restrict__ Wk,
                              const float* __restrict__ Wv, const float* __restrict__ Wo) {
    int i = blockIdx.x * blockDim.x + threadIdx.x;
    if (i >= 4 * E_ * E_) return;
    int z = i >> 20;
    int j = i & (E_ * E_ - 1);
    int n = j >> 10, k = j & 1023;
    const float* p = (z == 0) ? Wq : (z == 1) ? Wk : (z == 2) ? Wv : Wo;
    float v = p[j];
    int c = (k >> 3) & 7, w = k & 7;
    size_t idx = ((((size_t)z * NCH + (k >> 6)) * E_ + n) << 6)
               + (((c ^ (n & 7)) << 3) | w);
    g_wh[idx] = __float2half_rn(v);
}

// ---------------- HMMA fp16 2-pass GEMM: C = A @ W^T ----------------
// CTA tile 256x128, 8 warps (4M x 2N), warp tile 64x64, K chunks of 64.
// Decoupled producer/consumer: full[2] tx-mbarriers + empty[2] (8 warp arrivals).
#define TILE_AH 32768
#define TILE_BH 16384
#define STAGE_B (2*TILE_AH + TILE_BH)       // 80 KB
#define SMEM_BYTES (1024 + 2*STAGE_B)       // ~161 KB

__global__ __launch_bounds__(256) void gemm_f16_kernel(int mode, float* __restrict__ Cout)
{
    extern __shared__ char smraw[];
    const uint32_t raw = smem_u32(smraw);
    const uint32_t HDR = (raw + 1023) & ~1023u;
    const uint32_t TIL = HDR + 1024;
    const uint32_t FULL0 = HDR, FULL1 = HDR + 8;
    const uint32_t EMP0  = HDR + 16, EMP1 = HDR + 24;

    const int tid  = threadIdx.x;
    const int lane = tid & 31;
    const int wid  = tid >> 5;
    const int wm   = wid & 3;
    const int wn   = wid >> 2;
    const int sub  = lane >> 3;
    const int n0 = blockIdx.x << 7;
    const int m0 = blockIdx.y << 8;
    const int z  = (mode == 1) ? (int)blockIdx.z : 3;

    const __half* __restrict__ Ah = (mode == 1) ? g_xh : g_yh;
    const __half* __restrict__ Al = (mode == 1) ? g_xl : g_yl;

    if (tid == 0) {
        asm volatile("mbarrier.init.shared.b64 [%0], %1;" :: "r"(FULL0), "r"(1u) : "memory");
        asm volatile("mbarrier.init.shared.b64 [%0], %1;" :: "r"(FULL1), "r"(1u) : "memory");
        asm volatile("mbarrier.init.shared.b64 [%0], %1;" :: "r"(EMP0),  "r"(8u) : "memory");
        asm volatile("mbarrier.init.shared.b64 [%0], %1;" :: "r"(EMP1),  "r"(8u) : "memory");
    }
    __syncthreads();

    float acc[4][8][4];
    #pragma unroll
    for (int mi = 0; mi < 4; ++mi)
        #pragma unroll
        for (int ng = 0; ng < 8; ++ng)
            #pragma unroll
            for (int j = 0; j < 4; ++j) acc[mi][ng][j] = 0.f;

    auto issue = [&](int ci, int st) {
        uint32_t mb = HDR + st * 8;
        uint32_t db = TIL + st * STAGE_B;
        asm volatile("mbarrier.arrive.expect_tx.shared.b64 _, [%0], %1;"
                     :: "r"(mb), "r"((uint32_t)STAGE_B) : "memory");
        bulk_cp(db,               Ah   + (((size_t)ci * M_TOTAL + m0) << 6), TILE_AH, mb);
        bulk_cp(db + TILE_AH,     Al   + (((size_t)ci * M_TOTAL + m0) << 6), TILE_AH, mb);
        bulk_cp(db + 2 * TILE_AH, g_wh + ((((size_t)z * NCH + ci) * E_ + n0) << 6), TILE_BH, mb);
    };

    if (tid == 0) { issue(0, 0); issue(1, 1); }

    for (int i = 0; i < NCH; ++i) {
        const int st = i & 1;
        const uint32_t ph = (uint32_t)((i >> 1) & 1);
        mbar_wait(HDR + st * 8, ph);
        const uint32_t baseA = TIL + st * STAGE_B;
        const uint32_t baseB = baseA + 2 * TILE_AH;

        #pragma unroll
        for (int ks = 0; ks < 4; ++ks) {
            uint32_t Af[2][4][4];
            {
                const int ar0 = wm * 64 + (lane & 7) + ((sub & 1) << 3);
                const int akc = ks * 2 + (sub >> 1);
                #pragma unroll
                for (int mi = 0; mi < 4; ++mi) {
                    int r = ar0 + mi * 16;
                    uint32_t off = (uint32_t)(r * 128 + ((akc ^ (r & 7)) << 4));
                    LDSM4(Af[0][mi], baseA + off);
                    LDSM4(Af[1][mi], baseA + TILE_AH + off);
                }
            }
            uint32_t Bf[4][4];
            {
                const int br0 = wn * 64 + (lane & 7) + ((sub >> 1) << 3);
                const int bkc = ks * 2 + (sub & 1);
                #pragma unroll
                for (int g = 0; g < 4; ++g) {
                    int r = br0 + g * 16;
                    uint32_t off = (uint32_t)(r * 128 + ((bkc ^ (r & 7)) << 4));
                    LDSM4(Bf[g], baseB + off);
                }
            }
            #pragma unroll
            for (int mi = 0; mi < 4; ++mi)
                #pragma unroll
                for (int ng = 0; ng < 8; ++ng) {
                    const int g = ng >> 1, o = (ng & 1) << 1;
                    MMA16816(acc[mi][ng], Af[0][mi], &Bf[g][o]);   // hh
                    MMA16816(acc[mi][ng], Af[1][mi], &Bf[g][o]);   // lh
                }
        }
        // this warp is done reading stage st
        if (elect1()) mbar_arrive(HDR + 16 + st * 8);
        // producer: refill stage st with chunk i+2 once all warps are done
        if (tid == 0 && i + 2 < NCH) {
            mbar_wait(HDR + 16 + st * 8, ph);
            issue(i + 2, st);
        }
    }

    // ---- epilogue ----
    const int col2 = (lane & 3) << 1;
    const int h = (n0 >> 6) + wn;
    #pragma unroll
    for (int mi = 0; mi < 4; ++mi) {
        #pragma unroll
        for (int rr = 0; rr < 2; ++rr) {
            const int m = m0 + wm * 64 + mi * 16 + rr * 8 + (lane >> 2);
            if (mode == 0) {
                float* dp = Cout + (size_t)m * E_ + n0 + wn * 64;
                #pragma unroll
                for (int ng = 0; ng < 8; ++ng) {
                    float2 v = make_float2(acc[mi][ng][rr * 2], acc[mi][ng][rr * 2 + 1]);
                    *(float2*)(dp + ng * 8 + col2) = v;
                }
            } else {
                const int bb = m >> 11, ss = m & (S_ - 1);
                const int rsw = ss & 7;
                if (z == 2) {
                    size_t base = ((((size_t)(bb * H_ + h) * (S_ / 64) + (ss >> 6)) * 64
                                    + (ss & 63)) << 6);
                    #pragma unroll
                    for (int ng = 0; ng < 8; ++ng) {
                        int d = ng * 8 + col2;
                        uint32_t lo, hi = pack_hl(acc[mi][ng][rr*2], acc[mi][ng][rr*2+1], lo);
                        size_t idx = base + ((((d >> 3) ^ rsw) << 3) | (d & 7));
                        *(uint32_t*)&g_vf_h[idx] = hi;
                        *(uint32_t*)&g_vf_l[idx] = lo;
                    }
                } else {
                    float r1[4][2], r2[4][2];
                    #pragma unroll
                    for (int ng = 0; ng < 4; ++ng)
                        #pragma unroll
                        for (int jj = 0; jj < 2; ++jj) {
                            const int d = ng * 8 + col2 + jj;
                            float x1 = acc[mi][ng][rr * 2 + jj];
                            float x2 = acc[mi][ng + 4][rr * 2 + jj];
                            float c  = g_cos[(ss << 5) + d];
                            float sn = g_sin[(ss << 5) + d];
                            float v1 = x1 * c - x2 * sn;
                            float v2 = x2 * c + x1 * sn;
                            if (z == 0) { v1 *= 0.125f; v2 *= 0.125f; }
                            r1[ng][jj] = v1; r2[ng][jj] = v2;
                        }
                    size_t base;
                    __half *ph2, *pl2;
                    if (z == 0) {
                        base = ((((size_t)(bb * H_ + h) * (S_ / 128) + (ss >> 7)) * 128
                                 + (ss & 127)) << 6);
                        ph2 = g_qf_h; pl2 = g_qf_l;
                    } else {
                        base = ((((size_t)(bb * H_ + h) * (S_ / 64) + (ss >> 6)) * 64
                                 + (ss & 63)) << 6);
                        ph2 = g_kf_h; pl2 = g_kf_l;
                    }
                    #pragma unroll
                    for (int ng = 0; ng < 4; ++ng) {
                        int d = ng * 8 + col2;
                        uint32_t lo, hi = pack_hl(r1[ng][0], r1[ng][1], lo);
                        size_t idx = base + ((((d >> 3) ^ rsw) << 3) | (d & 7));
                        *(uint32_t*)&ph2[idx] = hi;
                        *(uint32_t*)&pl2[idx] = lo;
                        int d2 = d + 32;
                        uint32_t lo2, hi2 = pack_hl(r2[ng][0], r2[ng][1], lo2);
                        size_t idx2 = base + ((((d2 >> 3) ^ rsw) << 3) | (d2 & 7));
                        *(uint32_t*)&ph2[idx2] = hi2;
                        *(uint32_t*)&pl2[idx2] = lo2;
                    }
                }
            }
        }
    }
}

// ---------------- HMMA windowed flash attention (3-pass split) ----------------
#define Q_BYTES   16384
#define KV_TILE   8192
#define KV_STAGE  32768
#define SMEM_ATTN (1024 + 2*Q_BYTES + 2*KV_STAGE)

__global__ __launch_bounds__(256) void attn_kernel() {
    extern __shared__ char smraw[];
    const uint32_t raw = smem_u32(smraw);
    const uint32_t HDR  = (raw + 1023) & ~1023u;
    const uint32_t TILQ = HDR + 1024;
    const uint32_t KVB  = TILQ + 2 * Q_BYTES;
    // HDR+0: Q full; HDR+8,16: KV full; HDR+24,32: KV empty

    const int tid  = threadIdx.x;
    const int lane = tid & 31;
    const int wid  = tid >> 5;
    const int sub  = lane >> 3;
    const int g    = lane >> 2;
    const int t2   = (lane & 3) << 1;
    const int qt = blockIdx.x;
    const int q0 = qt << 7;
    const int h  = blockIdx.y;
    const int b  = blockIdx.z;
    const int bh = b * H_ + h;
    const int wrow = wid * 16;

    if (tid == 0) {
        asm volatile("mbarrier.init.shared.b64 [%0], %1;" :: "r"(HDR),      "r"(1u) : "memory");
        asm volatile("mbarrier.init.shared.b64 [%0], %1;" :: "r"(HDR + 8),  "r"(1u) : "memory");
        asm volatile("mbarrier.init.shared.b64 [%0], %1;" :: "r"(HDR + 16), "r"(1u) : "memory");
        asm volatile("mbarrier.init.shared.b64 [%0], %1;" :: "r"(HDR + 24), "r"(8u) : "memory");
        asm volatile("mbarrier.init.shared.b64 [%0], %1;" :: "r"(HDR + 32), "r"(8u) : "memory");
    }
    __syncthreads();

    const int kt0 = (q0 >= WIN_) ? ((q0 - WIN_ + 1) >> 6) : 0;
    const int kt1 = (q0 + 127) >> 6;
    const int nt  = kt1 - kt0 + 1;

    auto issueKV = [&](int kt, int j) {
        int st = j & 1;
        uint32_t mb = HDR + 8 + st * 8;
        uint32_t db = KVB + st * KV_STAGE;
        asm volatile("mbarrier.arrive.expect_tx.shared.b64 _, [%0], %1;"
                     :: "r"(mb), "r"((uint32_t)KV_STAGE) : "memory");
        const size_t tb = ((size_t)bh * (S_ / 64) + kt) << 12;
        bulk_cp(db,               g_kf_h + tb, KV_TILE, mb);
        bulk_cp(db + KV_TILE,     g_kf_l + tb, KV_TILE, mb);
        bulk_cp(db + 2 * KV_TILE, g_vf_h + tb, KV_TILE, mb);
        bulk_cp(db + 3 * KV_TILE, g_vf_l + tb, KV_TILE, mb);
    };

    if (tid == 0) {
        asm volatile("mbarrier.arrive.expect_tx.shared.b64 _, [%0], %1;"
                     :: "r"(HDR), "r"((uint32_t)(2 * Q_BYTES)) : "memory");
        const size_t qb = ((size_t)bh * (S_ / 128) + qt) << 13;
        bulk_cp(TILQ,           g_qf_h + qb, Q_BYTES, HDR);
        bulk_cp(TILQ + Q_BYTES, g_qf_l + qb, Q_BYTES, HDR);
        issueKV(kt0, 0);
        if (nt > 1) issueKV(kt0 + 1, 1);
    }

    uint32_t Aqh[4][4], Aql[4][4];
    mbar_wait(HDR, 0u);
    {
        const int r = wrow + (lane & 7) + ((sub & 1) << 3);
        #pragma unroll
        for (int ks = 0; ks < 4; ++ks) {
            uint32_t off = (uint32_t)(r * 128 + (((ks * 2 + (sub >> 1)) ^ (r & 7)) << 4));
            LDSM4(Aqh[ks], TILQ + off);
            LDSM4(Aql[ks], TILQ + Q_BYTES + off);
        }
    }

    float oacc[8][4];
    #pragma unroll
    for (int dg = 0; dg < 8; ++dg)
        #pragma unroll
        for (int j = 0; j < 4; ++j) oacc[dg][j] = 0.f;
    float mrow[2] = {-1e30f, -1e30f};
    float lrow[2] = {0.f, 0.f};
    const int sq0 = q0 + wrow + g;

    for (int j = 0; j < nt; ++j) {
        const int jb = (kt0 + j) << 6;
        const int st = j & 1;
        const uint32_t ph = (uint32_t)((j >> 1) & 1);
        mbar_wait(HDR + 8 + st * 8, ph);
        const uint32_t kb_h = KVB + st * KV_STAGE;
        const uint32_t kb_l = kb_h + KV_TILE;
        const uint32_t vb_h = kb_h + 2 * KV_TILE;
        const uint32_t vb_l = kb_h + 3 * KV_TILE;

        float sacc[8][4];
        #pragma unroll
        for (int cg = 0; cg < 8; ++cg)
            #pragma unroll
            for (int jj = 0; jj < 4; ++jj) sacc[cg][jj] = 0.f;

        #pragma unroll
        for (int ks = 0; ks < 4; ++ks) {
            #pragma unroll
            for (int kg = 0; kg < 4; ++kg) {
                uint32_t Bh[4], Bl[4];
                const int r = kg * 16 + (lane & 7) + ((sub >> 1) << 3);
                uint32_t off = (uint32_t)(r * 128 + (((ks * 2 + (sub & 1)) ^ (r & 7)) << 4));
                LDSM4(Bh, kb_h + off);
                LDSM4(Bl, kb_l + off);
                MMA16816(sacc[kg*2],   Aqh[ks], &Bh[0]);
                MMA16816(sacc[kg*2],   Aqh[ks], &Bl[0]);
                MMA16816(sacc[kg*2],   Aql[ks], &Bh[0]);
                MMA16816(sacc[kg*2+1], Aqh[ks], &Bh[2]);
                MMA16816(sacc[kg*2+1], Aqh[ks], &Bl[2]);
                MMA16816(sacc[kg*2+1], Aql[ks], &Bh[2]);
            }
        }

        float mx[2] = {-1e30f, -1e30f};
        #pragma unroll
        for (int cg = 0; cg < 8; ++cg) {
            const int jp = jb + cg * 8 + t2;
            #pragma unroll
            for (int rh = 0; rh < 2; ++rh) {
                const int sq = sq0 + rh * 8;
                #pragma unroll
                for (int jj = 0; jj < 2; ++jj) {
                    float& s = sacc[cg][rh * 2 + jj];
                    const int jpos = jp + jj;
                    bool ok = (jpos <= sq) && (sq - jpos < WIN_);
                    if (!ok) s = -1e30f;
                    mx[rh] = fmaxf(mx[rh], s);
                }
            }
        }
        #pragma unroll
        for (int off = 1; off < 4; off <<= 1) {
            mx[0] = fmaxf(mx[0], __shfl_xor_sync(0xFFFFFFFFu, mx[0], off));
            mx[1] = fmaxf(mx[1], __shfl_xor_sync(0xFFFFFFFFu, mx[1], off));
        }
        float mn[2], al[2], safe[2];
        #pragma unroll
        for (int rh = 0; rh < 2; ++rh) {
            mn[rh]   = fmaxf(mrow[rh], mx[rh]);
            al[rh]   = __expf(mrow[rh] - mn[rh]);
            safe[rh] = (mn[rh] < -1e29f) ? 0.f : mn[rh];
            mrow[rh] = mn[rh];
            lrow[rh] *= al[rh];
        }
        #pragma unroll
        for (int cg = 0; cg < 8; ++cg)
            #pragma unroll
            for (int rh = 0; rh < 2; ++rh)
                #pragma unroll
                for (int jj = 0; jj < 2; ++jj) {
                    float p = __expf(sacc[cg][rh * 2 + jj] - safe[rh]);
                    sacc[cg][rh * 2 + jj] = p;
                    lrow[rh] += p;
                }
        #pragma unroll
        for (int dg = 0; dg < 8; ++dg) {
            oacc[dg][0] *= al[0]; oacc[dg][1] *= al[0];
            oacc[dg][2] *= al[1]; oacc[dg][3] *= al[1];
        }

        #pragma unroll
        for (int kc4 = 0; kc4 < 4; ++kc4) {
            uint32_t ph4[4], pl4[4];
            ph4[0] = pack_hl(sacc[kc4*2][0],   sacc[kc4*2][1],   pl4[0]);
            ph4[1] = pack_hl(sacc[kc4*2][2],   sacc[kc4*2][3],   pl4[1]);
            ph4[2] = pack_hl(sacc[kc4*2+1][0], sacc[kc4*2+1][1], pl4[2]);
            ph4[3] = pack_hl(sacc[kc4*2+1][2], sacc[kc4*2+1][3], pl4[3]);
            const int r = kc4 * 16 + (lane & 7) + ((sub & 1) << 3);
            #pragma unroll
            for (int dg4 = 0; dg4 < 4; ++dg4) {
                uint32_t Vh[4], Vl[4];
                uint32_t off = (uint32_t)(r * 128 + (((dg4 * 2 + (sub >> 1)) ^ (r & 7)) << 4));
                LDSM4T(Vh, vb_h + off);
                LDSM4T(Vl, vb_l + off);
                MMA16816(oacc[dg4*2],   ph4, &Vh[0]);
                MMA16816(oacc[dg4*2],   ph4, &Vl[0]);
                MMA16816(oacc[dg4*2],   pl4, &Vh[0]);
                MMA16816(oacc[dg4*2+1], ph4, &Vh[2]);
                MMA16816(oacc[dg4*2+1], ph4, &Vl[2]);
                MMA16816(oacc[dg4*2+1], pl4, &Vh[2]);
            }
        }

        // done reading stage st
        if (elect1()) mbar_arrive(HDR + 24 + st * 8);
        if (tid == 0 && j + 2 < nt) {
            mbar_wait(HDR + 24 + st * 8, ph);
            issueKV(kt0 + j + 2, j + 2);
        }
    }

    #pragma unroll
    for (int off = 1; off < 4; off <<= 1) {
        lrow[0] += __shfl_xor_sync(0xFFFFFFFFu, lrow[0], off);
        lrow[1] += __shfl_xor_sync(0xFFFFFFFFu, lrow[1], off);
    }
    float inv[2] = {1.f / lrow[0], 1.f / lrow[1]};
    #pragma unroll
    for (int rh = 0; rh < 2; ++rh) {
        const int m = b * S_ + sq0 + rh * 8;
        const size_t base = ((size_t)h * M_TOTAL + m) << 6;
        const int rsw = m & 7;
        #pragma unroll
        for (int dg = 0; dg < 8; ++dg) {
            int d = dg * 8 + t2;
            float v0 = oacc[dg][rh * 2]     * inv[rh];
            float v1 = oacc[dg][rh * 2 + 1] * inv[rh];
            uint32_t lo, hi = pack_hl(v0, v1, lo);
            size_t idx = base + (((dg ^ rsw) << 3) | (d & 7));
            *(uint32_t*)&g_yh[idx] = hi;
            *(uint32_t*)&g_yl[idx] = lo;
        }
    }
}

// ---------------- launch ----------------
extern "C" void kernel_launch(void* const* d_in, const int* in_sizes, int n_in,
                              void* d_out, int out_size)
{
    const float* x  = (const float*)d_in[0];
    const float* Wq = (const float*)d_in[1];
    const float* Wk = (const float*)d_in[2];
    const float* Wv = (const float*)d_in[3];
    const float* Wo = (const float*)d_in[4];
    float* out = (float*)d_out;

    cudaFuncSetAttribute(gemm_f16_kernel,
                         cudaFuncAttributeMaxDynamicSharedMemorySize, SMEM_BYTES);
    cudaFuncSetAttribute(attn_kernel,
                         cudaFuncAttributeMaxDynamicSharedMemorySize, SMEM_ATTN);

    rope_table_kernel<<<(S_ * 32 + 255) / 256, 256>>>();
    conv_x_kernel<<<(M_TOTAL * E_) / 256, 256>>>(x);
    conv_w_kernel<<<(4 * E_ * E_) / 256, 256>>>(Wq, Wk, Wv, Wo);

    dim3 g1(E_ / 128, M_TOTAL / 256, 3);   // (8, 16, 3)
    gemm_f16_kernel<<<g1, 256, SMEM_BYTES>>>(1, nullptr);

    dim3 ga(S_ / 128, H_, B_);
    attn_kernel<<<ga, 256, SMEM_ATTN>>>();

    dim3 g2(E_ / 128, M_TOTAL / 256, 1);   // (8, 16)
    gemm_f16_kernel<<<g2, 256, SMEM_BYTES>>>(0, out);
}